// round 1
// baseline (speedup 1.0000x reference)
#include <cuda_runtime.h>

// ---------------------------------------------------------------------------
// WindowAttention: x[4096,49,384] -> qkv -> 12-head window attention (+rel-pos
// bias, +window mask, softmax) -> proj -> out[4096,49,384]
//
// Round-1 baseline: fp32 with packed fma.rn.f32x2 in the two big GEMMs.
// K1: qkv GEMM (200704x1152x384) with scatter epilogue to [3][B][H][49][32]
// K2: per-(window,head) attention, thread-per-query-row
// K3: proj GEMM (200704x384x384) -> d_out
// ---------------------------------------------------------------------------

#define BATCH   4096
#define NTOK    49
#define EMB     384
#define HEADS   12
#define HD      32
#define NWIN    64
#define MROWS   (BATCH * NTOK)        // 200704
#define QKV_O   (3 * EMB)             // 1152

// scratch (device globals: no allocation allowed in kernel_launch)
__device__ float g_qkv[(size_t)3 * BATCH * HEADS * NTOK * HD]; // 925 MB
__device__ float g_y[(size_t)MROWS * EMB];                     // 308 MB

__device__ __forceinline__ unsigned long long fma_f32x2(
    unsigned long long a, unsigned long long b, unsigned long long c) {
    unsigned long long d;
    asm("fma.rn.f32x2 %0, %1, %2, %3;" : "=l"(d) : "l"(a), "l"(b), "l"(c));
    return d;
}
__device__ __forceinline__ unsigned long long dup_f32(float v) {
    unsigned long long d;
    asm("mov.b64 %0, {%1, %1};" : "=l"(d) : "f"(v));
    return d;
}

// ---------------------------------------------------------------------------
// Tiled GEMM: C[m,o] = sum_k A[m,k] * W[o,k] + bias[o]
// BM=BN=128, BK=8, 256 threads, 8x8 per-thread microtile (rows paired f32x2).
// MODE 0: A = x, scatter into g_qkv ([s][b][h][n][d] layout), bias = qkv_b
// MODE 1: A = g_y, write out[m*384+o], bias = proj_b
// ---------------------------------------------------------------------------
template <int MODE>
__global__ void __launch_bounds__(256) gemm_kernel(
    const float* __restrict__ A, const float* __restrict__ W,
    const float* __restrict__ bias, float* __restrict__ out)
{
    __shared__ __align__(16) float As[8][128];
    __shared__ __align__(16) float Bs[8][128];

    const float* Aeff = (MODE == 1) ? (const float*)g_y : A;

    const int t     = threadIdx.x;
    const int mBase = blockIdx.y * 128;
    const int oBase = blockIdx.x * 128;
    const int tx    = t & 15;        // 0..15 (col groups of 8)
    const int ty    = t >> 4;        // 0..15 (row groups of 8)

    // loading assignment: each thread loads one float4 of A and one of W
    const int lr = t >> 1;           // row within tile (0..127)
    const int lk = (t & 1) * 4;      // k offset 0 or 4

    const float* Aptr = Aeff + (size_t)(mBase + lr) * EMB + lk;
    const float* Wptr = W    + (size_t)(oBase + lr) * EMB + lk;

    // 8 rows x 8 cols, rows packed in pairs: accp[p][j] = (row 2p, row 2p+1)
    unsigned long long accp[4][8];
#pragma unroll
    for (int p = 0; p < 4; p++)
#pragma unroll
        for (int j = 0; j < 8; j++) accp[p][j] = 0ull;

    for (int k0 = 0; k0 < EMB; k0 += 8) {
        float4 av = *(const float4*)(Aptr + k0);
        float4 wv = *(const float4*)(Wptr + k0);
        __syncthreads();   // previous iteration's compute must be done
        As[lk + 0][lr] = av.x; As[lk + 1][lr] = av.y;
        As[lk + 2][lr] = av.z; As[lk + 3][lr] = av.w;
        Bs[lk + 0][lr] = wv.x; Bs[lk + 1][lr] = wv.y;
        Bs[lk + 2][lr] = wv.z; Bs[lk + 3][lr] = wv.w;
        __syncthreads();
#pragma unroll
        for (int kk = 0; kk < 8; kk++) {
            // row pairs straight from smem as 64-bit packed f32x2
            const unsigned long long* Ap =
                (const unsigned long long*)&As[kk][ty * 8];
            unsigned long long rap[4];
#pragma unroll
            for (int p = 0; p < 4; p++) rap[p] = Ap[p];

            float4 b0 = *(const float4*)&Bs[kk][tx * 8];
            float4 b1 = *(const float4*)&Bs[kk][tx * 8 + 4];
            unsigned long long rbp[8];
            rbp[0] = dup_f32(b0.x); rbp[1] = dup_f32(b0.y);
            rbp[2] = dup_f32(b0.z); rbp[3] = dup_f32(b0.w);
            rbp[4] = dup_f32(b1.x); rbp[5] = dup_f32(b1.y);
            rbp[6] = dup_f32(b1.z); rbp[7] = dup_f32(b1.w);
#pragma unroll
            for (int p = 0; p < 4; p++)
#pragma unroll
                for (int j = 0; j < 8; j++)
                    accp[p][j] = fma_f32x2(rap[p], rbp[j], accp[p][j]);
        }
    }

    // epilogue
#pragma unroll
    for (int p = 0; p < 4; p++) {
#pragma unroll
        for (int j = 0; j < 8; j++) {
            float2 f2 = *(float2*)&accp[p][j];
            int m0 = mBase + ty * 8 + 2 * p;
            int o  = oBase + tx * 8 + j;
            float bo = bias[o];
            float v0 = f2.x + bo;
            float v1 = f2.y + bo;
            if (MODE == 0) {
                int s = o / EMB;
                int r = o - s * EMB;
                int h = r >> 5;
                int d = r & 31;
#pragma unroll
                for (int rr = 0; rr < 2; rr++) {
                    int m  = m0 + rr;
                    int b  = m / NTOK;
                    int nn = m - b * NTOK;
                    size_t idx = ((((size_t)s * BATCH + b) * HEADS + h) * NTOK
                                  + nn) * HD + d;
                    g_qkv[idx] = rr ? v1 : v0;
                }
            } else {
                out[(size_t)m0 * EMB + o]       = v0;
                out[(size_t)(m0 + 1) * EMB + o] = v1;
            }
        }
    }
}

// ---------------------------------------------------------------------------
// Attention: one CTA per (window b, head h). 64 threads; threads 0..48 each
// own one query row. K/V staged in smem (all reads are warp broadcasts).
// ---------------------------------------------------------------------------
__global__ void __launch_bounds__(64) attn_kernel(
    const float* __restrict__ mask, const float* __restrict__ rpb,
    const int* __restrict__ rel_idx)
{
    const int b = blockIdx.x;
    const int h = blockIdx.y;
    const int t = threadIdx.x;

    __shared__ __align__(16) float ks[NTOK * HD];
    __shared__ __align__(16) float vs[NTOK * HD];

    const size_t stride = (size_t)NTOK * HD;                     // 1568
    const size_t qoff = (((size_t)0 * BATCH + b) * HEADS + h) * stride;
    const size_t koff = (((size_t)1 * BATCH + b) * HEADS + h) * stride;
    const size_t voff = (((size_t)2 * BATCH + b) * HEADS + h) * stride;

    // stage K and V (392 float4 each)
    for (int i = t; i < (NTOK * HD) / 4; i += 64) {
        ((float4*)ks)[i] = ((const float4*)(g_qkv + koff))[i];
        ((float4*)vs)[i] = ((const float4*)(g_qkv + voff))[i];
    }
    __syncthreads();

    if (t < NTOK) {
        // load own query row into registers
        float q[HD];
#pragma unroll
        for (int i = 0; i < HD / 4; i++) {
            float4 v4 = ((const float4*)(g_qkv + qoff + (size_t)t * HD))[i];
            q[4 * i + 0] = v4.x; q[4 * i + 1] = v4.y;
            q[4 * i + 2] = v4.z; q[4 * i + 3] = v4.w;
        }

        const float scale = 0.17677669529663687f;  // 32^-0.5
        const float* mrow = mask + ((size_t)(b & (NWIN - 1)) * NTOK + t) * NTOK;
        const int*   ridx = rel_idx + t * NTOK;

        float logits[NTOK];
        float mx = -1e30f;
#pragma unroll
        for (int m = 0; m < NTOK; m++) {
            const float4* kp = (const float4*)(ks + m * HD);
            float s = 0.f;
#pragma unroll
            for (int kk = 0; kk < HD / 4; kk++) {
                float4 kv = kp[kk];
                s += q[4 * kk + 0] * kv.x;
                s += q[4 * kk + 1] * kv.y;
                s += q[4 * kk + 2] * kv.z;
                s += q[4 * kk + 3] * kv.w;
            }
            s = s * scale + rpb[ridx[m] * HEADS + h] + mrow[m];
            logits[m] = s;
            mx = fmaxf(mx, s);
        }
        float sum = 0.f;
#pragma unroll
        for (int m = 0; m < NTOK; m++) {
            float e = __expf(logits[m] - mx);
            logits[m] = e;
            sum += e;
        }
        const float inv = 1.0f / sum;

        float o[HD];
#pragma unroll
        for (int d = 0; d < HD; d++) o[d] = 0.f;
#pragma unroll
        for (int m = 0; m < NTOK; m++) {
            float a = logits[m] * inv;
            const float4* vp = (const float4*)(vs + m * HD);
#pragma unroll
            for (int d4 = 0; d4 < HD / 4; d4++) {
                float4 vv = vp[d4];
                o[4 * d4 + 0] += a * vv.x;
                o[4 * d4 + 1] += a * vv.y;
                o[4 * d4 + 2] += a * vv.z;
                o[4 * d4 + 3] += a * vv.w;
            }
        }
        // y[b*49+t][h*32 + d]
        float* yp = g_y + ((size_t)b * NTOK + t) * EMB + h * HD;
#pragma unroll
        for (int d4 = 0; d4 < HD / 4; d4++) {
            *(float4*)(yp + 4 * d4) =
                make_float4(o[4 * d4], o[4 * d4 + 1], o[4 * d4 + 2], o[4 * d4 + 3]);
        }
    }
}

// ---------------------------------------------------------------------------
extern "C" void kernel_launch(void* const* d_in, const int* in_sizes, int n_in,
                              void* d_out, int out_size)
{
    const float* x      = (const float*)d_in[0];   // [4096,49,384]
    const float* mask   = (const float*)d_in[1];   // [64,49,49]
    const float* qkv_w  = (const float*)d_in[2];   // [1152,384]
    const float* qkv_b  = (const float*)d_in[3];   // [1152]
    const float* proj_w = (const float*)d_in[4];   // [384,384]
    const float* proj_b = (const float*)d_in[5];   // [384]
    const float* rpb    = (const float*)d_in[6];   // [169,12]
    const int*   rel_idx= (const int*)  d_in[7];   // [49,49] int32
    float* out = (float*)d_out;

    // K1: qkv GEMM  (1152/128=9, 200704/128=1568)
    {
        dim3 grid(QKV_O / 128, MROWS / 128);
        gemm_kernel<0><<<grid, 256>>>(x, qkv_w, qkv_b, nullptr);
    }
    // K2: attention, one CTA per (window, head)
    {
        dim3 grid(BATCH, HEADS);
        attn_kernel<<<grid, 64>>>(mask, rpb, rel_idx);
    }
    // K3: proj GEMM (384/128=3, 1568)
    {
        dim3 grid(EMB / 128, MROWS / 128);
        gemm_kernel<1><<<grid, 256>>>(nullptr, proj_w, proj_b, out);
    }
}

// round 3
// speedup vs baseline: 2.6606x; 2.6606x over previous
#include <cuda_runtime.h>
#include <cstdint>

// ---------------------------------------------------------------------------
// WindowAttention round 2: tf32 mma.sync GEMMs + fp32 attention.
// K0 : round x / qkv_w / proj_w to tf32 (cvt.rna) -> g_x, g_wq, g_wp
// K1 : qkv GEMM (200704 x 1152 x 384) via m16n8k8 tf32 MMA, scatter to g_qkv
// K2 : per-(window,head) attention (fp32), epilogue rounds output to tf32 -> g_y
// K3 : proj GEMM (200704 x 384 x 384) via tf32 MMA -> d_out (+bias fp32)
// ---------------------------------------------------------------------------

#define BATCH   4096
#define NTOK    49
#define EMB     384
#define HEADS   12
#define HD      32
#define NWIN    64
#define MROWS   (BATCH * NTOK)        // 200704
#define QKV_O   (3 * EMB)             // 1152
#define KDIM    384

#define SSTR    36                    // smem row stride (floats): 4g+tig bank-free
#define ABUF    (128 * SSTR)          // floats per tile buffer
#define SMEM_BYTES (4 * ABUF * 4)     // A0,A1,B0,B1 = 73728 B

__device__ float g_qkv[(size_t)3 * BATCH * HEADS * NTOK * HD];
__device__ float g_y [(size_t)MROWS * EMB];
__device__ float g_x [(size_t)MROWS * EMB];
__device__ float g_wq[QKV_O * KDIM];
__device__ float g_wp[EMB * KDIM];

__device__ __forceinline__ float tf32r(float x) {
    uint32_t r;
    asm("cvt.rna.tf32.f32 %0, %1;" : "=r"(r) : "f"(x));
    return __uint_as_float(r);
}

__device__ __forceinline__ void cpa16(uint32_t dst, const float* src) {
    asm volatile("cp.async.ca.shared.global [%0], [%1], 16;"
                 :: "r"(dst), "l"(src));
}

// ---------------------------------------------------------------------------
// K0: elementwise round-to-tf32. DST: 0=g_x 1=g_wq 2=g_wp
// ---------------------------------------------------------------------------
template <int DST>
__global__ void cvt_tf32_kernel(const float4* __restrict__ in, int n4)
{
    int i = blockIdx.x * blockDim.x + threadIdx.x;
    if (i >= n4) return;
    float4 v = in[i];
    v.x = tf32r(v.x); v.y = tf32r(v.y); v.z = tf32r(v.z); v.w = tf32r(v.w);
    float4* outp = (DST == 0) ? (float4*)g_x
                 : (DST == 1) ? (float4*)g_wq : (float4*)g_wp;
    outp[i] = v;
}

// ---------------------------------------------------------------------------
// tf32 MMA GEMM: C[m,o] = sum_k A[m,k]*W[o,k] + bias[o]
// CTA 128x128, 8 warps (4 in M x 2 in N), warp tile 32x64, K-chunk 32,
// cp.async double buffer. MODE 0: A=g_x, W=g_wq, scatter->g_qkv.
// MODE 1: A=g_y, W=g_wp, write out.
// ---------------------------------------------------------------------------
template <int MODE>
__global__ void __launch_bounds__(256, 2) mma_gemm(
    const float* __restrict__ bias, float* __restrict__ out)
{
    extern __shared__ float smem[];   // [A0|A1|B0|B1] each 128*SSTR floats

    const float* A = (MODE == 0) ? g_x : g_y;
    const float* W = (MODE == 0) ? g_wq : g_wp;

    const int t     = threadIdx.x;
    const int mBase = blockIdx.y * 128;
    const int oBase = blockIdx.x * 128;
    const int warp  = t >> 5, lane = t & 31;
    const int g     = lane >> 2, tig = lane & 3;
    const int mOff  = (warp & 3) * 32;
    const int nOff  = (warp >> 2) * 64;

    const float* Ap = A + (size_t)mBase * KDIM;
    const float* Wp = W + (size_t)oBase * KDIM;

    // global->smem: each thread 4 float4 per matrix per chunk
    const int r0 = t >> 3;            // 0..31, +32*i
    const int kq = (t & 7) << 2;      // 0,4,..,28
    const uint32_t sA = (uint32_t)__cvta_generic_to_shared(smem);

    float acc[2][8][4];
#pragma unroll
    for (int mi = 0; mi < 2; mi++)
#pragma unroll
        for (int ni = 0; ni < 8; ni++)
#pragma unroll
            for (int j = 0; j < 4; j++) acc[mi][ni][j] = 0.f;

    auto load_chunk = [&](int k0, int buf) {
        uint32_t aB = sA + (uint32_t)(buf * ABUF) * 4u;
        uint32_t bB = sA + (uint32_t)((2 + buf) * ABUF) * 4u;
#pragma unroll
        for (int i = 0; i < 4; i++) {
            int row = r0 + 32 * i;
            cpa16(aB + (uint32_t)(row * SSTR + kq) * 4u,
                  Ap + (size_t)row * KDIM + k0 + kq);
            cpa16(bB + (uint32_t)(row * SSTR + kq) * 4u,
                  Wp + (size_t)row * KDIM + k0 + kq);
        }
        asm volatile("cp.async.commit_group;");
    };

    load_chunk(0, 0);

    const int NCH = KDIM / 32;        // 12
    for (int c = 0; c < NCH; c++) {
        if (c + 1 < NCH) {
            load_chunk((c + 1) * 32, (c + 1) & 1);
            asm volatile("cp.async.wait_group 1;");
        } else {
            asm volatile("cp.async.wait_group 0;");
        }
        __syncthreads();

        const float* Asb = smem + (c & 1) * ABUF;
        const float* Bsb = smem + (2 + (c & 1)) * ABUF;

#pragma unroll
        for (int kk = 0; kk < 32; kk += 8) {
            uint32_t a[2][4], b[8][2];
#pragma unroll
            for (int mi = 0; mi < 2; mi++) {
                int r = mOff + mi * 16 + g;
                a[mi][0] = __float_as_uint(Asb[r * SSTR + kk + tig]);
                a[mi][1] = __float_as_uint(Asb[(r + 8) * SSTR + kk + tig]);
                a[mi][2] = __float_as_uint(Asb[r * SSTR + kk + tig + 4]);
                a[mi][3] = __float_as_uint(Asb[(r + 8) * SSTR + kk + tig + 4]);
            }
#pragma unroll
            for (int ni = 0; ni < 8; ni++) {
                int cc = nOff + ni * 8 + g;
                b[ni][0] = __float_as_uint(Bsb[cc * SSTR + kk + tig]);
                b[ni][1] = __float_as_uint(Bsb[cc * SSTR + kk + tig + 4]);
            }
#pragma unroll
            for (int mi = 0; mi < 2; mi++)
#pragma unroll
                for (int ni = 0; ni < 8; ni++) {
                    asm volatile(
                        "mma.sync.aligned.m16n8k8.row.col.f32.tf32.tf32.f32 "
                        "{%0,%1,%2,%3},{%4,%5,%6,%7},{%8,%9},{%0,%1,%2,%3};"
                        : "+f"(acc[mi][ni][0]), "+f"(acc[mi][ni][1]),
                          "+f"(acc[mi][ni][2]), "+f"(acc[mi][ni][3])
                        : "r"(a[mi][0]), "r"(a[mi][1]),
                          "r"(a[mi][2]), "r"(a[mi][3]),
                          "r"(b[ni][0]), "r"(b[ni][1]));
                }
        }
        __syncthreads();
    }

    // epilogue: c0,c1 = (g, 2tig..2tig+1); c2,c3 = (g+8, ...)
#pragma unroll
    for (int mi = 0; mi < 2; mi++) {
#pragma unroll
        for (int ni = 0; ni < 8; ni++) {
            int col = oBase + nOff + ni * 8 + 2 * tig;
            float b0 = __ldg(bias + col);
            float b1 = __ldg(bias + col + 1);
#pragma unroll
            for (int half = 0; half < 2; half++) {
                int m = mBase + mOff + mi * 16 + g + half * 8;
                float v0 = acc[mi][ni][2 * half + 0] + b0;
                float v1 = acc[mi][ni][2 * half + 1] + b1;
                if (MODE == 0) {
                    int s = col / EMB;
                    int r = col - s * EMB;
                    int h = r >> 5, d = r & 31;
                    int bb = m / NTOK;
                    int nn = m - bb * NTOK;
                    size_t idx = ((((size_t)s * BATCH + bb) * HEADS + h) * NTOK
                                  + nn) * HD + d;
                    *(float2*)&g_qkv[idx] = make_float2(v0, v1);
                } else {
                    *(float2*)&out[(size_t)m * EMB + col] = make_float2(v0, v1);
                }
            }
        }
    }
}

// ---------------------------------------------------------------------------
// K2: attention. One CTA per (window b, head h); threads 0..48 own query rows.
// Output rounded to tf32 (free pre-rounding for K3's MMA).
// ---------------------------------------------------------------------------
__global__ void __launch_bounds__(64) attn_kernel(
    const float* __restrict__ mask, const float* __restrict__ rpb,
    const int* __restrict__ rel_idx)
{
    const int b = blockIdx.x;
    const int h = blockIdx.y;
    const int t = threadIdx.x;

    __shared__ __align__(16) float ks[NTOK * HD];
    __shared__ __align__(16) float vs[NTOK * HD];

    const size_t stride = (size_t)NTOK * HD;
    const size_t qoff = (((size_t)0 * BATCH + b) * HEADS + h) * stride;
    const size_t koff = (((size_t)1 * BATCH + b) * HEADS + h) * stride;
    const size_t voff = (((size_t)2 * BATCH + b) * HEADS + h) * stride;

    for (int i = t; i < (NTOK * HD) / 4; i += 64) {
        ((float4*)ks)[i] = ((const float4*)(g_qkv + koff))[i];
        ((float4*)vs)[i] = ((const float4*)(g_qkv + voff))[i];
    }
    __syncthreads();

    if (t < NTOK) {
        float q[HD];
#pragma unroll
        for (int i = 0; i < HD / 4; i++) {
            float4 v4 = ((const float4*)(g_qkv + qoff + (size_t)t * HD))[i];
            q[4 * i + 0] = v4.x; q[4 * i + 1] = v4.y;
            q[4 * i + 2] = v4.z; q[4 * i + 3] = v4.w;
        }

        const float scale = 0.17677669529663687f;
        const float* mrow = mask + ((size_t)(b & (NWIN - 1)) * NTOK + t) * NTOK;
        const int*   ridx = rel_idx + t * NTOK;

        float logits[NTOK];
        float mx = -1e30f;
#pragma unroll
        for (int m = 0; m < NTOK; m++) {
            const float4* kp = (const float4*)(ks + m * HD);
            float s = 0.f;
#pragma unroll
            for (int kk = 0; kk < HD / 4; kk++) {
                float4 kv = kp[kk];
                s += q[4 * kk + 0] * kv.x;
                s += q[4 * kk + 1] * kv.y;
                s += q[4 * kk + 2] * kv.z;
                s += q[4 * kk + 3] * kv.w;
            }
            s = s * scale + rpb[ridx[m] * HEADS + h] + mrow[m];
            logits[m] = s;
            mx = fmaxf(mx, s);
        }
        float sum = 0.f;
#pragma unroll
        for (int m = 0; m < NTOK; m++) {
            float e = __expf(logits[m] - mx);
            logits[m] = e;
            sum += e;
        }
        const float inv = 1.0f / sum;

        float o[HD];
#pragma unroll
        for (int d = 0; d < HD; d++) o[d] = 0.f;
#pragma unroll
        for (int m = 0; m < NTOK; m++) {
            float a = logits[m] * inv;
            const float4* vp = (const float4*)(vs + m * HD);
#pragma unroll
            for (int d4 = 0; d4 < HD / 4; d4++) {
                float4 vv = vp[d4];
                o[4 * d4 + 0] += a * vv.x;
                o[4 * d4 + 1] += a * vv.y;
                o[4 * d4 + 2] += a * vv.z;
                o[4 * d4 + 3] += a * vv.w;
            }
        }
        float* yp = g_y + ((size_t)b * NTOK + t) * EMB + h * HD;
#pragma unroll
        for (int d4 = 0; d4 < HD / 4; d4++) {
            *(float4*)(yp + 4 * d4) = make_float4(
                tf32r(o[4 * d4 + 0]), tf32r(o[4 * d4 + 1]),
                tf32r(o[4 * d4 + 2]), tf32r(o[4 * d4 + 3]));
        }
    }
}

// ---------------------------------------------------------------------------
extern "C" void kernel_launch(void* const* d_in, const int* in_sizes, int n_in,
                              void* d_out, int out_size)
{
    const float* x      = (const float*)d_in[0];
    const float* mask   = (const float*)d_in[1];
    const float* qkv_w  = (const float*)d_in[2];
    const float* qkv_b  = (const float*)d_in[3];
    const float* proj_w = (const float*)d_in[4];
    const float* proj_b = (const float*)d_in[5];
    const float* rpb    = (const float*)d_in[6];
    const int*   rel_idx= (const int*)  d_in[7];
    float* out = (float*)d_out;

    cudaFuncSetAttribute(mma_gemm<0>,
        cudaFuncAttributeMaxDynamicSharedMemorySize, SMEM_BYTES);
    cudaFuncSetAttribute(mma_gemm<1>,
        cudaFuncAttributeMaxDynamicSharedMemorySize, SMEM_BYTES);

    // K0: tf32 rounding pre-pass
    {
        int n4 = MROWS * EMB / 4;
        cvt_tf32_kernel<0><<<(n4 + 255) / 256, 256>>>((const float4*)x, n4);
        int w4 = QKV_O * KDIM / 4;
        cvt_tf32_kernel<1><<<(w4 + 255) / 256, 256>>>((const float4*)qkv_w, w4);
        int p4 = EMB * KDIM / 4;
        cvt_tf32_kernel<2><<<(p4 + 255) / 256, 256>>>((const float4*)proj_w, p4);
    }
    // K1: qkv GEMM
    {
        dim3 grid(QKV_O / 128, MROWS / 128);
        mma_gemm<0><<<grid, 256, SMEM_BYTES>>>(qkv_b, nullptr);
    }
    // K2: attention
    {
        dim3 grid(BATCH, HEADS);
        attn_kernel<<<grid, 64>>>(mask, rpb, rel_idx);
    }
    // K3: proj GEMM
    {
        dim3 grid(EMB / 128, MROWS / 128);
        mma_gemm<1><<<grid, 256, SMEM_BYTES>>>(proj_b, out);
    }
}

// round 4
// speedup vs baseline: 2.6854x; 1.0093x over previous
#include <cuda_runtime.h>
#include <cstdint>

// ---------------------------------------------------------------------------
// WindowAttention round 3:
//  K0: round x / qkv_w / proj_w to tf32 (cvt.rna)
//  K1: qkv GEMM, tf32 mma.sync, warp tile 64x64 (4 warps / CTA 128x128)
//  K2: attention with f32x2-packed dot products / accumulation
//  K3: proj GEMM, same GEMM engine
// ---------------------------------------------------------------------------

#define BATCH   4096
#define NTOK    49
#define EMB     384
#define HEADS   12
#define HD      32
#define NWIN    64
#define MROWS   (BATCH * NTOK)        // 200704
#define QKV_O   (3 * EMB)             // 1152
#define KDIM    384

#define SSTR    36                    // smem row stride (floats), bank-free
#define ABUF    (128 * SSTR)
#define SMEM_BYTES (4 * ABUF * 4)     // 73728 B

typedef unsigned long long ull;

__device__ float g_qkv[(size_t)3 * BATCH * HEADS * NTOK * HD];
__device__ float g_y [(size_t)MROWS * EMB];
__device__ float g_x [(size_t)MROWS * EMB];
__device__ float g_wq[QKV_O * KDIM];
__device__ float g_wp[EMB * KDIM];

__device__ __forceinline__ float tf32r(float x) {
    uint32_t r;
    asm("cvt.rna.tf32.f32 %0, %1;" : "=r"(r) : "f"(x));
    return __uint_as_float(r);
}
__device__ __forceinline__ ull fma2(ull a, ull b, ull c) {
    ull d;
    asm("fma.rn.f32x2 %0, %1, %2, %3;" : "=l"(d) : "l"(a), "l"(b), "l"(c));
    return d;
}
__device__ __forceinline__ ull dup2(float v) {
    ull d;
    asm("mov.b64 %0, {%1, %1};" : "=l"(d) : "f"(v));
    return d;
}
__device__ __forceinline__ void cpa16(uint32_t dst, const float* src) {
    asm volatile("cp.async.ca.shared.global [%0], [%1], 16;"
                 :: "r"(dst), "l"(src));
}

// ---------------------------------------------------------------------------
// K0: elementwise round-to-tf32
// ---------------------------------------------------------------------------
template <int DST>
__global__ void cvt_tf32_kernel(const float4* __restrict__ in, int n4)
{
    int i = blockIdx.x * blockDim.x + threadIdx.x;
    if (i >= n4) return;
    float4 v = in[i];
    v.x = tf32r(v.x); v.y = tf32r(v.y); v.z = tf32r(v.z); v.w = tf32r(v.w);
    float4* outp = (DST == 0) ? (float4*)g_x
                 : (DST == 1) ? (float4*)g_wq : (float4*)g_wp;
    outp[i] = v;
}

// ---------------------------------------------------------------------------
// tf32 MMA GEMM: C[m,o] = sum_k A[m,k]*W[o,k] + bias[o]
// CTA 128x128, 4 warps (2Mx2N), warp tile 64x64, K-chunk 32, cp.async 2-buf.
// MODE 0: A=g_x, W=g_wq, scatter->g_qkv.  MODE 1: A=g_y, W=g_wp, ->out.
// ---------------------------------------------------------------------------
template <int MODE>
__global__ void __launch_bounds__(128, 2) mma_gemm(
    const float* __restrict__ bias, float* __restrict__ out)
{
    extern __shared__ float smem[];   // [A0|A1|B0|B1]

    const float* A = (MODE == 0) ? g_x : g_y;
    const float* W = (MODE == 0) ? g_wq : g_wp;

    const int t     = threadIdx.x;
    const int mBase = blockIdx.y * 128;
    const int oBase = blockIdx.x * 128;
    const int warp  = t >> 5, lane = t & 31;
    const int g     = lane >> 2, tig = lane & 3;
    const int mOff  = (warp & 1) * 64;
    const int nOff  = (warp >> 1) * 64;

    const float* Ap = A + (size_t)mBase * KDIM;
    const float* Wp = W + (size_t)oBase * KDIM;

    const int lr = t >> 3;            // 0..15
    const int kq = (t & 7) << 2;      // 0..28
    const uint32_t sA = (uint32_t)__cvta_generic_to_shared(smem);

    float acc[4][8][4];
#pragma unroll
    for (int mi = 0; mi < 4; mi++)
#pragma unroll
        for (int ni = 0; ni < 8; ni++)
#pragma unroll
            for (int j = 0; j < 4; j++) acc[mi][ni][j] = 0.f;

    auto load_chunk = [&](int k0, int buf) {
        uint32_t aB = sA + (uint32_t)(buf * ABUF) * 4u;
        uint32_t bB = sA + (uint32_t)((2 + buf) * ABUF) * 4u;
#pragma unroll
        for (int i = 0; i < 8; i++) {
            int row = lr + 16 * i;
            cpa16(aB + (uint32_t)(row * SSTR + kq) * 4u,
                  Ap + (size_t)row * KDIM + k0 + kq);
            cpa16(bB + (uint32_t)(row * SSTR + kq) * 4u,
                  Wp + (size_t)row * KDIM + k0 + kq);
        }
        asm volatile("cp.async.commit_group;");
    };

    load_chunk(0, 0);

    const int NCH = KDIM / 32;        // 12
    for (int c = 0; c < NCH; c++) {
        if (c + 1 < NCH) {
            load_chunk((c + 1) * 32, (c + 1) & 1);
            asm volatile("cp.async.wait_group 1;");
        } else {
            asm volatile("cp.async.wait_group 0;");
        }
        __syncthreads();

        const float* Asb = smem + (c & 1) * ABUF;
        const float* Bsb = smem + (2 + (c & 1)) * ABUF;

#pragma unroll
        for (int kk = 0; kk < 32; kk += 8) {
            uint32_t a[4][4], b[8][2];
#pragma unroll
            for (int mi = 0; mi < 4; mi++) {
                int r = mOff + mi * 16 + g;
                a[mi][0] = __float_as_uint(Asb[r * SSTR + kk + tig]);
                a[mi][1] = __float_as_uint(Asb[(r + 8) * SSTR + kk + tig]);
                a[mi][2] = __float_as_uint(Asb[r * SSTR + kk + tig + 4]);
                a[mi][3] = __float_as_uint(Asb[(r + 8) * SSTR + kk + tig + 4]);
            }
#pragma unroll
            for (int ni = 0; ni < 8; ni++) {
                int cc = nOff + ni * 8 + g;
                b[ni][0] = __float_as_uint(Bsb[cc * SSTR + kk + tig]);
                b[ni][1] = __float_as_uint(Bsb[cc * SSTR + kk + tig + 4]);
            }
#pragma unroll
            for (int mi = 0; mi < 4; mi++)
#pragma unroll
                for (int ni = 0; ni < 8; ni++) {
                    asm volatile(
                        "mma.sync.aligned.m16n8k8.row.col.f32.tf32.tf32.f32 "
                        "{%0,%1,%2,%3},{%4,%5,%6,%7},{%8,%9},{%0,%1,%2,%3};"
                        : "+f"(acc[mi][ni][0]), "+f"(acc[mi][ni][1]),
                          "+f"(acc[mi][ni][2]), "+f"(acc[mi][ni][3])
                        : "r"(a[mi][0]), "r"(a[mi][1]),
                          "r"(a[mi][2]), "r"(a[mi][3]),
                          "r"(b[ni][0]), "r"(b[ni][1]));
                }
        }
        __syncthreads();
    }

#pragma unroll
    for (int mi = 0; mi < 4; mi++) {
#pragma unroll
        for (int ni = 0; ni < 8; ni++) {
            int col = oBase + nOff + ni * 8 + 2 * tig;
            float b0 = __ldg(bias + col);
            float b1 = __ldg(bias + col + 1);
#pragma unroll
            for (int half = 0; half < 2; half++) {
                int m = mBase + mOff + mi * 16 + g + half * 8;
                float v0 = acc[mi][ni][2 * half + 0] + b0;
                float v1 = acc[mi][ni][2 * half + 1] + b1;
                if (MODE == 0) {
                    int s = col / EMB;
                    int r = col - s * EMB;
                    int h = r >> 5, d = r & 31;
                    int bb = m / NTOK;
                    int nn = m - bb * NTOK;
                    size_t idx = ((((size_t)s * BATCH + bb) * HEADS + h) * NTOK
                                  + nn) * HD + d;
                    *(float2*)&g_qkv[idx] = make_float2(v0, v1);
                } else {
                    *(float2*)&out[(size_t)m * EMB + col] = make_float2(v0, v1);
                }
            }
        }
    }
}

// ---------------------------------------------------------------------------
// K2: attention, f32x2-packed. One CTA per (b,h); threads 0..48 = query rows.
// ---------------------------------------------------------------------------
__global__ void __launch_bounds__(64) attn_kernel(
    const float* __restrict__ mask, const float* __restrict__ rpb,
    const int* __restrict__ rel_idx)
{
    const int b = blockIdx.x;
    const int h = blockIdx.y;
    const int t = threadIdx.x;

    __shared__ __align__(16) float ks[NTOK * HD];
    __shared__ __align__(16) float vs[NTOK * HD];

    const size_t stride = (size_t)NTOK * HD;
    const size_t qoff = (((size_t)0 * BATCH + b) * HEADS + h) * stride;
    const size_t koff = (((size_t)1 * BATCH + b) * HEADS + h) * stride;
    const size_t voff = (((size_t)2 * BATCH + b) * HEADS + h) * stride;

    for (int i = t; i < (NTOK * HD) / 4; i += 64) {
        ((float4*)ks)[i] = ((const float4*)(g_qkv + koff))[i];
        ((float4*)vs)[i] = ((const float4*)(g_qkv + voff))[i];
    }
    __syncthreads();

    if (t < NTOK) {
        // query row packed as 16 f32x2
        ull q2[HD / 2];
#pragma unroll
        for (int i = 0; i < HD / 4; i++) {
            ulonglong2 v = ((const ulonglong2*)(g_qkv + qoff + (size_t)t * HD))[i];
            q2[2 * i] = v.x; q2[2 * i + 1] = v.y;
        }

        const float scale = 0.17677669529663687f;
        const float* mrow = mask + ((size_t)(b & (NWIN - 1)) * NTOK + t) * NTOK;
        const int*   ridx = rel_idx + t * NTOK;

        float logits[NTOK];
        float mx = -1e30f;
#pragma unroll 7
        for (int m = 0; m < NTOK; m++) {
            const ull* kp = (const ull*)(ks + m * HD);
            ull s2 = 0;
#pragma unroll
            for (int j = 0; j < HD / 2; j++) s2 = fma2(q2[j], kp[j], s2);
            float2 sf = *(float2*)&s2;
            float s = (sf.x + sf.y) * scale
                    + __ldg(rpb + ridx[m] * HEADS + h) + mrow[m];
            logits[m] = s;
            mx = fmaxf(mx, s);
        }
        float sum = 0.f;
#pragma unroll 7
        for (int m = 0; m < NTOK; m++) {
            float e = __expf(logits[m] - mx);
            logits[m] = e;
            sum += e;
        }
        const float inv = 1.0f / sum;

        ull o2[HD / 2];
#pragma unroll
        for (int j = 0; j < HD / 2; j++) o2[j] = 0;
#pragma unroll 7
        for (int m = 0; m < NTOK; m++) {
            ull a2 = dup2(logits[m] * inv);
            const ull* vp = (const ull*)(vs + m * HD);
#pragma unroll
            for (int j = 0; j < HD / 2; j++) o2[j] = fma2(a2, vp[j], o2[j]);
        }

        float* yp = g_y + ((size_t)b * NTOK + t) * EMB + h * HD;
#pragma unroll
        for (int j = 0; j < HD / 4; j++) {
            float2 e0 = *(float2*)&o2[2 * j];
            float2 e1 = *(float2*)&o2[2 * j + 1];
            *(float4*)(yp + 4 * j) = make_float4(
                tf32r(e0.x), tf32r(e0.y), tf32r(e1.x), tf32r(e1.y));
        }
    }
}

// ---------------------------------------------------------------------------
extern "C" void kernel_launch(void* const* d_in, const int* in_sizes, int n_in,
                              void* d_out, int out_size)
{
    const float* x      = (const float*)d_in[0];
    const float* mask   = (const float*)d_in[1];
    const float* qkv_w  = (const float*)d_in[2];
    const float* qkv_b  = (const float*)d_in[3];
    const float* proj_w = (const float*)d_in[4];
    const float* proj_b = (const float*)d_in[5];
    const float* rpb    = (const float*)d_in[6];
    const int*   rel_idx= (const int*)  d_in[7];
    float* out = (float*)d_out;

    cudaFuncSetAttribute(mma_gemm<0>,
        cudaFuncAttributeMaxDynamicSharedMemorySize, SMEM_BYTES);
    cudaFuncSetAttribute(mma_gemm<1>,
        cudaFuncAttributeMaxDynamicSharedMemorySize, SMEM_BYTES);

    // K0: tf32 rounding pre-pass
    {
        int n4 = MROWS * EMB / 4;
        cvt_tf32_kernel<0><<<(n4 + 255) / 256, 256>>>((const float4*)x, n4);
        int w4 = QKV_O * KDIM / 4;
        cvt_tf32_kernel<1><<<(w4 + 255) / 256, 256>>>((const float4*)qkv_w, w4);
        int p4 = EMB * KDIM / 4;
        cvt_tf32_kernel<2><<<(p4 + 255) / 256, 256>>>((const float4*)proj_w, p4);
    }
    // K1: qkv GEMM
    {
        dim3 grid(QKV_O / 128, MROWS / 128);
        mma_gemm<0><<<grid, 128, SMEM_BYTES>>>(qkv_b, nullptr);
    }
    // K2: attention
    {
        dim3 grid(BATCH, HEADS);
        attn_kernel<<<grid, 64>>>(mask, rpb, rel_idx);
    }
    // K3: proj GEMM
    {
        dim3 grid(EMB / 128, MROWS / 128);
        mma_gemm<1><<<grid, 128, SMEM_BYTES>>>(proj_b, out);
    }
}

// round 6
// speedup vs baseline: 3.1591x; 1.1764x over previous
#include <cuda_runtime.h>
#include <cstdint>

// ---------------------------------------------------------------------------
// WindowAttention round 5:
//  K0 : round x / qkv_w / proj_w to tf32; precompute combined bias+mask table
//  K1 : qkv GEMM, tf32 mma.sync (round-3 engine, verified)
//  K2 : attention via m16n8k8 tf32 MMA; QK uses hi/lo 3x split for accuracy
//  K3 : proj GEMM
// ---------------------------------------------------------------------------

#define BATCH   4096
#define NTOK    49
#define EMB     384
#define HEADS   12
#define HD      32
#define NWIN    64
#define MROWS   (BATCH * NTOK)        // 200704
#define QKV_O   (3 * EMB)             // 1152
#define KDIM    384

#define SSTR    36
#define ABUF    (128 * SSTR)
#define SMEM_BYTES (4 * ABUF * 4)     // 73728 B

// padded attention dims
#define NTP     64                    // padded query rows
#define NSP     56                    // padded kv tokens

typedef unsigned long long ull;

__device__ float g_qkv[(size_t)3 * BATCH * HEADS * NTOK * HD];
__device__ float g_y [(size_t)MROWS * EMB];
__device__ float g_x [(size_t)MROWS * EMB];
__device__ float g_wq[QKV_O * KDIM];
__device__ float g_wp[EMB * KDIM];
__device__ float g_comb[(size_t)NWIN * HEADS * NTP * NSP];   // 11 MB

__device__ __forceinline__ float tf32r(float x) {
    uint32_t r;
    asm("cvt.rna.tf32.f32 %0, %1;" : "=r"(r) : "f"(x));
    return __uint_as_float(r);
}
__device__ __forceinline__ void cpa16(uint32_t dst, const float* src) {
    asm volatile("cp.async.ca.shared.global [%0], [%1], 16;"
                 :: "r"(dst), "l"(src));
}
__device__ __forceinline__ void mma_tf32(
    float c[4], const uint32_t a[4], uint32_t b0, uint32_t b1)
{
    asm volatile(
        "mma.sync.aligned.m16n8k8.row.col.f32.tf32.tf32.f32 "
        "{%0,%1,%2,%3},{%4,%5,%6,%7},{%8,%9},{%0,%1,%2,%3};"
        : "+f"(c[0]), "+f"(c[1]), "+f"(c[2]), "+f"(c[3])
        : "r"(a[0]), "r"(a[1]), "r"(a[2]), "r"(a[3]), "r"(b0), "r"(b1));
}

// ---------------------------------------------------------------------------
// K0a: elementwise round-to-tf32
// ---------------------------------------------------------------------------
template <int DST>
__global__ void cvt_tf32_kernel(const float4* __restrict__ in, int n4)
{
    int i = blockIdx.x * blockDim.x + threadIdx.x;
    if (i >= n4) return;
    float4 v = in[i];
    v.x = tf32r(v.x); v.y = tf32r(v.y); v.z = tf32r(v.z); v.w = tf32r(v.w);
    float4* outp = (DST == 0) ? (float4*)g_x
                 : (DST == 1) ? (float4*)g_wq : (float4*)g_wp;
    outp[i] = v;
}

// ---------------------------------------------------------------------------
// K0b: combined bias+mask table, padded:
// g_comb[w][h][i][j] = mask[w,i,j] + rpb[rel_idx[i,j], h]   (i,j < 49)
//                    = -1e30                                 otherwise
// ---------------------------------------------------------------------------
__global__ void prep_bias(const float* __restrict__ mask,
                          const float* __restrict__ rpb,
                          const int* __restrict__ rel_idx)
{
    int idx = blockIdx.x * blockDim.x + threadIdx.x;
    const int total = NWIN * HEADS * NTP * NSP;
    if (idx >= total) return;
    int j = idx % NSP;
    int i = (idx / NSP) % NTP;
    int h = (idx / (NSP * NTP)) % HEADS;
    int w = idx / (NSP * NTP * HEADS);
    float v = -1e30f;
    if (i < NTOK && j < NTOK)
        v = mask[((size_t)w * NTOK + i) * NTOK + j]
          + rpb[rel_idx[i * NTOK + j] * HEADS + h];
    g_comb[idx] = v;
}

// ---------------------------------------------------------------------------
// K1/K3: tf32 MMA GEMM (round-3 engine, verified correct)
// ---------------------------------------------------------------------------
template <int MODE>
__global__ void __launch_bounds__(128, 2) mma_gemm(
    const float* __restrict__ bias, float* __restrict__ out)
{
    extern __shared__ float smem[];

    const float* A = (MODE == 0) ? g_x : g_y;
    const float* W = (MODE == 0) ? g_wq : g_wp;

    const int t     = threadIdx.x;
    const int mBase = blockIdx.y * 128;
    const int oBase = blockIdx.x * 128;
    const int warp  = t >> 5, lane = t & 31;
    const int g     = lane >> 2, tig = lane & 3;
    const int mOff  = (warp & 1) * 64;
    const int nOff  = (warp >> 1) * 64;

    const float* Ap = A + (size_t)mBase * KDIM;
    const float* Wp = W + (size_t)oBase * KDIM;

    const int lr = t >> 3;
    const int kq = (t & 7) << 2;
    const uint32_t sA = (uint32_t)__cvta_generic_to_shared(smem);

    float acc[4][8][4];
#pragma unroll
    for (int mi = 0; mi < 4; mi++)
#pragma unroll
        for (int ni = 0; ni < 8; ni++)
#pragma unroll
            for (int j = 0; j < 4; j++) acc[mi][ni][j] = 0.f;

    auto load_chunk = [&](int k0, int buf) {
        uint32_t aB = sA + (uint32_t)(buf * ABUF) * 4u;
        uint32_t bB = sA + (uint32_t)((2 + buf) * ABUF) * 4u;
#pragma unroll
        for (int i = 0; i < 8; i++) {
            int row = lr + 16 * i;
            cpa16(aB + (uint32_t)(row * SSTR + kq) * 4u,
                  Ap + (size_t)row * KDIM + k0 + kq);
            cpa16(bB + (uint32_t)(row * SSTR + kq) * 4u,
                  Wp + (size_t)row * KDIM + k0 + kq);
        }
        asm volatile("cp.async.commit_group;");
    };

    load_chunk(0, 0);

    const int NCHk = KDIM / 32;
    for (int c = 0; c < NCHk; c++) {
        if (c + 1 < NCHk) {
            load_chunk((c + 1) * 32, (c + 1) & 1);
            asm volatile("cp.async.wait_group 1;");
        } else {
            asm volatile("cp.async.wait_group 0;");
        }
        __syncthreads();

        const float* Asb = smem + (c & 1) * ABUF;
        const float* Bsb = smem + (2 + (c & 1)) * ABUF;

#pragma unroll
        for (int kk = 0; kk < 32; kk += 8) {
            uint32_t a[4][4], b[8][2];
#pragma unroll
            for (int mi = 0; mi < 4; mi++) {
                int r = mOff + mi * 16 + g;
                a[mi][0] = __float_as_uint(Asb[r * SSTR + kk + tig]);
                a[mi][1] = __float_as_uint(Asb[(r + 8) * SSTR + kk + tig]);
                a[mi][2] = __float_as_uint(Asb[r * SSTR + kk + tig + 4]);
                a[mi][3] = __float_as_uint(Asb[(r + 8) * SSTR + kk + tig + 4]);
            }
#pragma unroll
            for (int ni = 0; ni < 8; ni++) {
                int cc = nOff + ni * 8 + g;
                b[ni][0] = __float_as_uint(Bsb[cc * SSTR + kk + tig]);
                b[ni][1] = __float_as_uint(Bsb[cc * SSTR + kk + tig + 4]);
            }
#pragma unroll
            for (int mi = 0; mi < 4; mi++)
#pragma unroll
                for (int ni = 0; ni < 8; ni++)
                    mma_tf32(acc[mi][ni], a[mi], b[ni][0], b[ni][1]);
        }
        __syncthreads();
    }

#pragma unroll
    for (int mi = 0; mi < 4; mi++) {
#pragma unroll
        for (int ni = 0; ni < 8; ni++) {
            int col = oBase + nOff + ni * 8 + 2 * tig;
            float b0 = __ldg(bias + col);
            float b1 = __ldg(bias + col + 1);
#pragma unroll
            for (int half = 0; half < 2; half++) {
                int m = mBase + mOff + mi * 16 + g + half * 8;
                float v0 = acc[mi][ni][2 * half + 0] + b0;
                float v1 = acc[mi][ni][2 * half + 1] + b1;
                if (MODE == 0) {
                    int s = col / EMB;
                    int r = col - s * EMB;
                    int h = r >> 5;
                    int bb = m / NTOK;
                    int nn = m - bb * NTOK;
                    size_t idx = ((((size_t)s * BATCH + bb) * HEADS + h) * NTOK
                                  + nn) * HD + ((r & 31));
                    *(float2*)&g_qkv[idx] = make_float2(v0, v1);
                } else {
                    *(float2*)&out[(size_t)m * EMB + col] = make_float2(v0, v1);
                }
            }
        }
    }
}

// ---------------------------------------------------------------------------
// K2: tensor-core attention. One CTA (128 thr) per (b,h).
// Warp w owns query rows [16w, 16w+16). QK = tf32 3x split; AV = tf32.
// ---------------------------------------------------------------------------
#define QSTR 33
#define VSTR 57
#define OFF_QH 0
#define OFF_QL (OFF_QH + NTP * QSTR)          // 2112
#define OFF_KH (OFF_QL + NTP * QSTR)          // 4224
#define OFF_KL (OFF_KH + NSP * QSTR)          // 6072
#define OFF_VT (OFF_KL + NSP * QSTR)          // 7920
#define SM_TOT (OFF_VT + HD * VSTR)           // 9744 floats

__global__ void __launch_bounds__(128) attn_kernel()
{
    const int b = blockIdx.x;
    const int h = blockIdx.y;
    const int tid = threadIdx.x;

    __shared__ __align__(16) float sm[SM_TOT];

    // zero (covers all padding)
    for (int i = tid; i < SM_TOT; i += 128) sm[i] = 0.f;
    __syncthreads();

    const size_t stride = (size_t)NTOK * HD;
    const size_t qoff = (((size_t)0 * BATCH + b) * HEADS + h) * stride;
    const size_t koff = (((size_t)1 * BATCH + b) * HEADS + h) * stride;
    const size_t voff = (((size_t)2 * BATCH + b) * HEADS + h) * stride;

    // stage Q (hi/lo), K (hi/lo), V^T; 392 float4 each
    for (int i = tid; i < (NTOK * HD) / 4; i += 128) {
        int row = i >> 3, col = (i & 7) * 4;
        float4 q = ((const float4*)(g_qkv + qoff))[i];
        float4 k = ((const float4*)(g_qkv + koff))[i];
        float4 v = ((const float4*)(g_qkv + voff))[i];
        float qa[4] = {q.x, q.y, q.z, q.w};
        float ka[4] = {k.x, k.y, k.z, k.w};
        float va[4] = {v.x, v.y, v.z, v.w};
#pragma unroll
        for (int c = 0; c < 4; c++) {
            float qh = tf32r(qa[c]);
            float kh = tf32r(ka[c]);
            sm[OFF_QH + row * QSTR + col + c] = qh;
            sm[OFF_QL + row * QSTR + col + c] = tf32r(qa[c] - qh);
            sm[OFF_KH + row * QSTR + col + c] = kh;
            sm[OFF_KL + row * QSTR + col + c] = tf32r(ka[c] - kh);
            sm[OFF_VT + (col + c) * VSTR + row] = tf32r(va[c]);
        }
    }
    __syncthreads();

    const int wid  = tid >> 5, lane = tid & 31;
    const int g    = lane >> 2, t = lane & 3;
    const int r0   = wid * 16 + g;          // query rows r0, r0+8

    // A-fragments of Q (hi and lo), all 4 k-steps, hoisted
    uint32_t ah[4][4], al[4][4];
#pragma unroll
    for (int kc = 0; kc < 4; kc++) {
        int base = kc * 8 + t;
        ah[kc][0] = __float_as_uint(sm[OFF_QH + r0 * QSTR + base]);
        ah[kc][1] = __float_as_uint(sm[OFF_QH + (r0 + 8) * QSTR + base]);
        ah[kc][2] = __float_as_uint(sm[OFF_QH + r0 * QSTR + base + 4]);
        ah[kc][3] = __float_as_uint(sm[OFF_QH + (r0 + 8) * QSTR + base + 4]);
        al[kc][0] = __float_as_uint(sm[OFF_QL + r0 * QSTR + base]);
        al[kc][1] = __float_as_uint(sm[OFF_QL + (r0 + 8) * QSTR + base]);
        al[kc][2] = __float_as_uint(sm[OFF_QL + r0 * QSTR + base + 4]);
        al[kc][3] = __float_as_uint(sm[OFF_QL + (r0 + 8) * QSTR + base + 4]);
    }

    // QK^T: 7 n-tiles of 8 kv tokens
    float c[7][4];
#pragma unroll
    for (int j = 0; j < 7; j++)
#pragma unroll
        for (int q = 0; q < 4; q++) c[j][q] = 0.f;

#pragma unroll
    for (int j = 0; j < 7; j++) {
#pragma unroll
        for (int kc = 0; kc < 4; kc++) {
            int krow = (j * 8 + g) * QSTR + kc * 8 + t;
            uint32_t bh0 = __float_as_uint(sm[OFF_KH + krow]);
            uint32_t bh1 = __float_as_uint(sm[OFF_KH + krow + 4]);
            uint32_t bl0 = __float_as_uint(sm[OFF_KL + krow]);
            uint32_t bl1 = __float_as_uint(sm[OFF_KL + krow + 4]);
            mma_tf32(c[j], ah[kc], bh0, bh1);
            mma_tf32(c[j], ah[kc], bl0, bl1);
            mma_tf32(c[j], al[kc], bh0, bh1);
        }
    }

    // logits = c*scale + comb
    const float scale = 0.17677669529663687f;
    const float* comb = g_comb
        + (((size_t)(b & (NWIN - 1)) * HEADS + h) * NTP) * NSP;
#pragma unroll
    for (int j = 0; j < 7; j++) {
        float2 m0 = *(const float2*)(comb + r0 * NSP + j * 8 + 2 * t);
        float2 m1 = *(const float2*)(comb + (r0 + 8) * NSP + j * 8 + 2 * t);
        c[j][0] = fmaf(c[j][0], scale, m0.x);
        c[j][1] = fmaf(c[j][1], scale, m0.y);
        c[j][2] = fmaf(c[j][2], scale, m1.x);
        c[j][3] = fmaf(c[j][3], scale, m1.y);
    }

    // softmax (rows r0 and r0+8): max, exp, sum (quad shfl reductions)
    float mx0 = -1e30f, mx1 = -1e30f;
#pragma unroll
    for (int j = 0; j < 7; j++) {
        mx0 = fmaxf(mx0, fmaxf(c[j][0], c[j][1]));
        mx1 = fmaxf(mx1, fmaxf(c[j][2], c[j][3]));
    }
    mx0 = fmaxf(mx0, __shfl_xor_sync(0xffffffffu, mx0, 1));
    mx0 = fmaxf(mx0, __shfl_xor_sync(0xffffffffu, mx0, 2));
    mx1 = fmaxf(mx1, __shfl_xor_sync(0xffffffffu, mx1, 1));
    mx1 = fmaxf(mx1, __shfl_xor_sync(0xffffffffu, mx1, 2));

    float s0 = 0.f, s1 = 0.f;
#pragma unroll
    for (int j = 0; j < 7; j++) {
        float e0 = __expf(c[j][0] - mx0);
        float e1 = __expf(c[j][1] - mx0);
        float e2 = __expf(c[j][2] - mx1);
        float e3 = __expf(c[j][3] - mx1);
        s0 += e0 + e1; s1 += e2 + e3;
        c[j][0] = tf32r(e0); c[j][1] = tf32r(e1);
        c[j][2] = tf32r(e2); c[j][3] = tf32r(e3);
    }
    s0 += __shfl_xor_sync(0xffffffffu, s0, 1);
    s0 += __shfl_xor_sync(0xffffffffu, s0, 2);
    s1 += __shfl_xor_sync(0xffffffffu, s1, 1);
    s1 += __shfl_xor_sync(0xffffffffu, s1, 2);
    const float inv0 = 1.0f / s0, inv1 = 1.0f / s1;

    // AV: P (c-frag -> a-frag via shfl) x V^T
    float acc[4][4];
#pragma unroll
    for (int n = 0; n < 4; n++)
#pragma unroll
        for (int q = 0; q < 4; q++) acc[n][q] = 0.f;

#pragma unroll
    for (int j = 0; j < 7; j++) {
        int src = (g << 2) + (t >> 1);
        float v0 = __shfl_sync(0xffffffffu, c[j][0], src);
        float v1 = __shfl_sync(0xffffffffu, c[j][1], src);
        float v2 = __shfl_sync(0xffffffffu, c[j][2], src);
        float v3 = __shfl_sync(0xffffffffu, c[j][3], src);
        float w0 = __shfl_sync(0xffffffffu, c[j][0], src + 2);
        float w1 = __shfl_sync(0xffffffffu, c[j][1], src + 2);
        float w2 = __shfl_sync(0xffffffffu, c[j][2], src + 2);
        float w3 = __shfl_sync(0xffffffffu, c[j][3], src + 2);
        uint32_t a[4];
        a[0] = __float_as_uint((t & 1) ? v1 : v0);
        a[1] = __float_as_uint((t & 1) ? v3 : v2);
        a[2] = __float_as_uint((t & 1) ? w1 : w0);
        a[3] = __float_as_uint((t & 1) ? w3 : w2);
#pragma unroll
        for (int n = 0; n < 4; n++) {
            int vrow = (n * 8 + g) * VSTR + j * 8 + t;
            uint32_t b0 = __float_as_uint(sm[OFF_VT + vrow]);
            uint32_t b1 = __float_as_uint(sm[OFF_VT + vrow + 4]);
            mma_tf32(acc[n], a, b0, b1);
        }
    }

    // write out (rows < 49), normalized + tf32-rounded (feeds K3's MMA)
#pragma unroll
    for (int n = 0; n < 4; n++) {
        int col = h * HD + n * 8 + 2 * t;
        if (r0 < NTOK) {
            float2 o = make_float2(tf32r(acc[n][0] * inv0),
                                   tf32r(acc[n][1] * inv0));
            *(float2*)&g_y[((size_t)b * NTOK + r0) * EMB + col] = o;
        }
        if (r0 + 8 < NTOK) {
            float2 o = make_float2(tf32r(acc[n][2] * inv1),
                                   tf32r(acc[n][3] * inv1));
            *(float2*)&g_y[((size_t)b * NTOK + r0 + 8) * EMB + col] = o;
        }
    }
}

// ---------------------------------------------------------------------------
extern "C" void kernel_launch(void* const* d_in, const int* in_sizes, int n_in,
                              void* d_out, int out_size)
{
    const float* x      = (const float*)d_in[0];
    const float* mask   = (const float*)d_in[1];
    const float* qkv_w  = (const float*)d_in[2];
    const float* qkv_b  = (const float*)d_in[3];
    const float* proj_w = (const float*)d_in[4];
    const float* proj_b = (const float*)d_in[5];
    const float* rpb    = (const float*)d_in[6];
    const int*   rel_idx= (const int*)  d_in[7];
    float* out = (float*)d_out;

    cudaFuncSetAttribute(mma_gemm<0>,
        cudaFuncAttributeMaxDynamicSharedMemorySize, SMEM_BYTES);
    cudaFuncSetAttribute(mma_gemm<1>,
        cudaFuncAttributeMaxDynamicSharedMemorySize, SMEM_BYTES);

    // K0: tf32 rounding + combined bias table
    {
        int n4 = MROWS * EMB / 4;
        cvt_tf32_kernel<0><<<(n4 + 255) / 256, 256>>>((const float4*)x, n4);
        int w4 = QKV_O * KDIM / 4;
        cvt_tf32_kernel<1><<<(w4 + 255) / 256, 256>>>((const float4*)qkv_w, w4);
        int p4 = EMB * KDIM / 4;
        cvt_tf32_kernel<2><<<(p4 + 255) / 256, 256>>>((const float4*)proj_w, p4);
        int nb = NWIN * HEADS * NTP * NSP;
        prep_bias<<<(nb + 255) / 256, 256>>>(mask, rpb, rel_idx);
    }
    // K1: qkv GEMM
    {
        dim3 grid(QKV_O / 128, MROWS / 128);
        mma_gemm<0><<<grid, 128, SMEM_BYTES>>>(qkv_b, nullptr);
    }
    // K2: attention
    {
        dim3 grid(BATCH, HEADS);
        attn_kernel<<<grid, 128>>>();
    }
    // K3: proj GEMM
    {
        dim3 grid(EMB / 128, MROWS / 128);
        mma_gemm<1><<<grid, 128, SMEM_BYTES>>>(proj_b, out);
    }
}

// round 7
// speedup vs baseline: 3.1595x; 1.0001x over previous
#include <cuda_runtime.h>
#include <cstdint>

// ---------------------------------------------------------------------------
// WindowAttention round 5:
//  K0 : round x / qkv_w / proj_w to tf32; precompute combined bias+mask table
//  K1 : qkv GEMM, tf32 mma.sync (round-3 engine, verified)
//  K2 : attention via m16n8k8 tf32 MMA; QK uses hi/lo 3x split for accuracy
//  K3 : proj GEMM
// ---------------------------------------------------------------------------

#define BATCH   4096
#define NTOK    49
#define EMB     384
#define HEADS   12
#define HD      32
#define NWIN    64
#define MROWS   (BATCH * NTOK)        // 200704
#define QKV_O   (3 * EMB)             // 1152
#define KDIM    384

#define SSTR    36
#define ABUF    (128 * SSTR)
#define SMEM_BYTES (4 * ABUF * 4)     // 73728 B

// padded attention dims
#define NTP     64                    // padded query rows
#define NSP     56                    // padded kv tokens

typedef unsigned long long ull;

__device__ float g_qkv[(size_t)3 * BATCH * HEADS * NTOK * HD];
__device__ float g_y [(size_t)MROWS * EMB];
__device__ float g_x [(size_t)MROWS * EMB];
__device__ float g_wq[QKV_O * KDIM];
__device__ float g_wp[EMB * KDIM];
__device__ float g_comb[(size_t)NWIN * HEADS * NTP * NSP];   // 11 MB

__device__ __forceinline__ float tf32r(float x) {
    uint32_t r;
    asm("cvt.rna.tf32.f32 %0, %1;" : "=r"(r) : "f"(x));
    return __uint_as_float(r);
}
__device__ __forceinline__ void cpa16(uint32_t dst, const float* src) {
    asm volatile("cp.async.ca.shared.global [%0], [%1], 16;"
                 :: "r"(dst), "l"(src));
}
__device__ __forceinline__ void mma_tf32(
    float c[4], const uint32_t a[4], uint32_t b0, uint32_t b1)
{
    asm volatile(
        "mma.sync.aligned.m16n8k8.row.col.f32.tf32.tf32.f32 "
        "{%0,%1,%2,%3},{%4,%5,%6,%7},{%8,%9},{%0,%1,%2,%3};"
        : "+f"(c[0]), "+f"(c[1]), "+f"(c[2]), "+f"(c[3])
        : "r"(a[0]), "r"(a[1]), "r"(a[2]), "r"(a[3]), "r"(b0), "r"(b1));
}

// ---------------------------------------------------------------------------
// K0a: elementwise round-to-tf32
// ---------------------------------------------------------------------------
template <int DST>
__global__ void cvt_tf32_kernel(const float4* __restrict__ in, int n4)
{
    int i = blockIdx.x * blockDim.x + threadIdx.x;
    if (i >= n4) return;
    float4 v = in[i];
    v.x = tf32r(v.x); v.y = tf32r(v.y); v.z = tf32r(v.z); v.w = tf32r(v.w);
    float4* outp = (DST == 0) ? (float4*)g_x
                 : (DST == 1) ? (float4*)g_wq : (float4*)g_wp;
    outp[i] = v;
}

// ---------------------------------------------------------------------------
// K0b: combined bias+mask table, padded:
// g_comb[w][h][i][j] = mask[w,i,j] + rpb[rel_idx[i,j], h]   (i,j < 49)
//                    = -1e30                                 otherwise
// ---------------------------------------------------------------------------
__global__ void prep_bias(const float* __restrict__ mask,
                          const float* __restrict__ rpb,
                          const int* __restrict__ rel_idx)
{
    int idx = blockIdx.x * blockDim.x + threadIdx.x;
    const int total = NWIN * HEADS * NTP * NSP;
    if (idx >= total) return;
    int j = idx % NSP;
    int i = (idx / NSP) % NTP;
    int h = (idx / (NSP * NTP)) % HEADS;
    int w = idx / (NSP * NTP * HEADS);
    float v = -1e30f;
    if (i < NTOK && j < NTOK)
        v = mask[((size_t)w * NTOK + i) * NTOK + j]
          + rpb[rel_idx[i * NTOK + j] * HEADS + h];
    g_comb[idx] = v;
}

// ---------------------------------------------------------------------------
// K1/K3: tf32 MMA GEMM (round-3 engine, verified correct)
// ---------------------------------------------------------------------------
template <int MODE>
__global__ void __launch_bounds__(128, 2) mma_gemm(
    const float* __restrict__ bias, float* __restrict__ out)
{
    extern __shared__ float smem[];

    const float* A = (MODE == 0) ? g_x : g_y;
    const float* W = (MODE == 0) ? g_wq : g_wp;

    const int t     = threadIdx.x;
    const int mBase = blockIdx.y * 128;
    const int oBase = blockIdx.x * 128;
    const int warp  = t >> 5, lane = t & 31;
    const int g     = lane >> 2, tig = lane & 3;
    const int mOff  = (warp & 1) * 64;
    const int nOff  = (warp >> 1) * 64;

    const float* Ap = A + (size_t)mBase * KDIM;
    const float* Wp = W + (size_t)oBase * KDIM;

    const int lr = t >> 3;
    const int kq = (t & 7) << 2;
    const uint32_t sA = (uint32_t)__cvta_generic_to_shared(smem);

    float acc[4][8][4];
#pragma unroll
    for (int mi = 0; mi < 4; mi++)
#pragma unroll
        for (int ni = 0; ni < 8; ni++)
#pragma unroll
            for (int j = 0; j < 4; j++) acc[mi][ni][j] = 0.f;

    auto load_chunk = [&](int k0, int buf) {
        uint32_t aB = sA + (uint32_t)(buf * ABUF) * 4u;
        uint32_t bB = sA + (uint32_t)((2 + buf) * ABUF) * 4u;
#pragma unroll
        for (int i = 0; i < 8; i++) {
            int row = lr + 16 * i;
            cpa16(aB + (uint32_t)(row * SSTR + kq) * 4u,
                  Ap + (size_t)row * KDIM + k0 + kq);
            cpa16(bB + (uint32_t)(row * SSTR + kq) * 4u,
                  Wp + (size_t)row * KDIM + k0 + kq);
        }
        asm volatile("cp.async.commit_group;");
    };

    load_chunk(0, 0);

    const int NCHk = KDIM / 32;
    for (int c = 0; c < NCHk; c++) {
        if (c + 1 < NCHk) {
            load_chunk((c + 1) * 32, (c + 1) & 1);
            asm volatile("cp.async.wait_group 1;");
        } else {
            asm volatile("cp.async.wait_group 0;");
        }
        __syncthreads();

        const float* Asb = smem + (c & 1) * ABUF;
        const float* Bsb = smem + (2 + (c & 1)) * ABUF;

#pragma unroll
        for (int kk = 0; kk < 32; kk += 8) {
            uint32_t a[4][4], b[8][2];
#pragma unroll
            for (int mi = 0; mi < 4; mi++) {
                int r = mOff + mi * 16 + g;
                a[mi][0] = __float_as_uint(Asb[r * SSTR + kk + tig]);
                a[mi][1] = __float_as_uint(Asb[(r + 8) * SSTR + kk + tig]);
                a[mi][2] = __float_as_uint(Asb[r * SSTR + kk + tig + 4]);
                a[mi][3] = __float_as_uint(Asb[(r + 8) * SSTR + kk + tig + 4]);
            }
#pragma unroll
            for (int ni = 0; ni < 8; ni++) {
                int cc = nOff + ni * 8 + g;
                b[ni][0] = __float_as_uint(Bsb[cc * SSTR + kk + tig]);
                b[ni][1] = __float_as_uint(Bsb[cc * SSTR + kk + tig + 4]);
            }
#pragma unroll
            for (int mi = 0; mi < 4; mi++)
#pragma unroll
                for (int ni = 0; ni < 8; ni++)
                    mma_tf32(acc[mi][ni], a[mi], b[ni][0], b[ni][1]);
        }
        __syncthreads();
    }

#pragma unroll
    for (int mi = 0; mi < 4; mi++) {
#pragma unroll
        for (int ni = 0; ni < 8; ni++) {
            int col = oBase + nOff + ni * 8 + 2 * tig;
            float b0 = __ldg(bias + col);
            float b1 = __ldg(bias + col + 1);
#pragma unroll
            for (int half = 0; half < 2; half++) {
                int m = mBase + mOff + mi * 16 + g + half * 8;
                float v0 = acc[mi][ni][2 * half + 0] + b0;
                float v1 = acc[mi][ni][2 * half + 1] + b1;
                if (MODE == 0) {
                    int s = col / EMB;
                    int r = col - s * EMB;
                    int h = r >> 5;
                    int bb = m / NTOK;
                    int nn = m - bb * NTOK;
                    size_t idx = ((((size_t)s * BATCH + bb) * HEADS + h) * NTOK
                                  + nn) * HD + ((r & 31));
                    *(float2*)&g_qkv[idx] = make_float2(v0, v1);
                } else {
                    *(float2*)&out[(size_t)m * EMB + col] = make_float2(v0, v1);
                }
            }
        }
    }
}

// ---------------------------------------------------------------------------
// K2: tensor-core attention. One CTA (128 thr) per (b,h).
// Warp w owns query rows [16w, 16w+16). QK = tf32 3x split; AV = tf32.
// ---------------------------------------------------------------------------
#define QSTR 33
#define VSTR 57
#define OFF_QH 0
#define OFF_QL (OFF_QH + NTP * QSTR)          // 2112
#define OFF_KH (OFF_QL + NTP * QSTR)          // 4224
#define OFF_KL (OFF_KH + NSP * QSTR)          // 6072
#define OFF_VT (OFF_KL + NSP * QSTR)          // 7920
#define SM_TOT (OFF_VT + HD * VSTR)           // 9744 floats

__global__ void __launch_bounds__(128) attn_kernel()
{
    const int b = blockIdx.x;
    const int h = blockIdx.y;
    const int tid = threadIdx.x;

    __shared__ __align__(16) float sm[SM_TOT];

    // zero (covers all padding)
    for (int i = tid; i < SM_TOT; i += 128) sm[i] = 0.f;
    __syncthreads();

    const size_t stride = (size_t)NTOK * HD;
    const size_t qoff = (((size_t)0 * BATCH + b) * HEADS + h) * stride;
    const size_t koff = (((size_t)1 * BATCH + b) * HEADS + h) * stride;
    const size_t voff = (((size_t)2 * BATCH + b) * HEADS + h) * stride;

    // stage Q (hi/lo), K (hi/lo), V^T; 392 float4 each
    for (int i = tid; i < (NTOK * HD) / 4; i += 128) {
        int row = i >> 3, col = (i & 7) * 4;
        float4 q = ((const float4*)(g_qkv + qoff))[i];
        float4 k = ((const float4*)(g_qkv + koff))[i];
        float4 v = ((const float4*)(g_qkv + voff))[i];
        float qa[4] = {q.x, q.y, q.z, q.w};
        float ka[4] = {k.x, k.y, k.z, k.w};
        float va[4] = {v.x, v.y, v.z, v.w};
#pragma unroll
        for (int c = 0; c < 4; c++) {
            float qh = tf32r(qa[c]);
            float kh = tf32r(ka[c]);
            sm[OFF_QH + row * QSTR + col + c] = qh;
            sm[OFF_QL + row * QSTR + col + c] = tf32r(qa[c] - qh);
            sm[OFF_KH + row * QSTR + col + c] = kh;
            sm[OFF_KL + row * QSTR + col + c] = tf32r(ka[c] - kh);
            sm[OFF_VT + (col + c) * VSTR + row] = tf32r(va[c]);
        }
    }
    __syncthreads();

    const int wid  = tid >> 5, lane = tid & 31;
    const int g    = lane >> 2, t = lane & 3;
    const int r0   = wid * 16 + g;          // query rows r0, r0+8

    // A-fragments of Q (hi and lo), all 4 k-steps, hoisted
    uint32_t ah[4][4], al[4][4];
#pragma unroll
    for (int kc = 0; kc < 4; kc++) {
        int base = kc * 8 + t;
        ah[kc][0] = __float_as_uint(sm[OFF_QH + r0 * QSTR + base]);
        ah[kc][1] = __float_as_uint(sm[OFF_QH + (r0 + 8) * QSTR + base]);
        ah[kc][2] = __float_as_uint(sm[OFF_QH + r0 * QSTR + base + 4]);
        ah[kc][3] = __float_as_uint(sm[OFF_QH + (r0 + 8) * QSTR + base + 4]);
        al[kc][0] = __float_as_uint(sm[OFF_QL + r0 * QSTR + base]);
        al[kc][1] = __float_as_uint(sm[OFF_QL + (r0 + 8) * QSTR + base]);
        al[kc][2] = __float_as_uint(sm[OFF_QL + r0 * QSTR + base + 4]);
        al[kc][3] = __float_as_uint(sm[OFF_QL + (r0 + 8) * QSTR + base + 4]);
    }

    // QK^T: 7 n-tiles of 8 kv tokens
    float c[7][4];
#pragma unroll
    for (int j = 0; j < 7; j++)
#pragma unroll
        for (int q = 0; q < 4; q++) c[j][q] = 0.f;

#pragma unroll
    for (int j = 0; j < 7; j++) {
#pragma unroll
        for (int kc = 0; kc < 4; kc++) {
            int krow = (j * 8 + g) * QSTR + kc * 8 + t;
            uint32_t bh0 = __float_as_uint(sm[OFF_KH + krow]);
            uint32_t bh1 = __float_as_uint(sm[OFF_KH + krow + 4]);
            uint32_t bl0 = __float_as_uint(sm[OFF_KL + krow]);
            uint32_t bl1 = __float_as_uint(sm[OFF_KL + krow + 4]);
            mma_tf32(c[j], ah[kc], bh0, bh1);
            mma_tf32(c[j], ah[kc], bl0, bl1);
            mma_tf32(c[j], al[kc], bh0, bh1);
        }
    }

    // logits = c*scale + comb
    const float scale = 0.17677669529663687f;
    const float* comb = g_comb
        + (((size_t)(b & (NWIN - 1)) * HEADS + h) * NTP) * NSP;
#pragma unroll
    for (int j = 0; j < 7; j++) {
        float2 m0 = *(const float2*)(comb + r0 * NSP + j * 8 + 2 * t);
        float2 m1 = *(const float2*)(comb + (r0 + 8) * NSP + j * 8 + 2 * t);
        c[j][0] = fmaf(c[j][0], scale, m0.x);
        c[j][1] = fmaf(c[j][1], scale, m0.y);
        c[j][2] = fmaf(c[j][2], scale, m1.x);
        c[j][3] = fmaf(c[j][3], scale, m1.y);
    }

    // softmax (rows r0 and r0+8): max, exp, sum (quad shfl reductions)
    float mx0 = -1e30f, mx1 = -1e30f;
#pragma unroll
    for (int j = 0; j < 7; j++) {
        mx0 = fmaxf(mx0, fmaxf(c[j][0], c[j][1]));
        mx1 = fmaxf(mx1, fmaxf(c[j][2], c[j][3]));
    }
    mx0 = fmaxf(mx0, __shfl_xor_sync(0xffffffffu, mx0, 1));
    mx0 = fmaxf(mx0, __shfl_xor_sync(0xffffffffu, mx0, 2));
    mx1 = fmaxf(mx1, __shfl_xor_sync(0xffffffffu, mx1, 1));
    mx1 = fmaxf(mx1, __shfl_xor_sync(0xffffffffu, mx1, 2));

    float s0 = 0.f, s1 = 0.f;
#pragma unroll
    for (int j = 0; j < 7; j++) {
        float e0 = __expf(c[j][0] - mx0);
        float e1 = __expf(c[j][1] - mx0);
        float e2 = __expf(c[j][2] - mx1);
        float e3 = __expf(c[j][3] - mx1);
        s0 += e0 + e1; s1 += e2 + e3;
        c[j][0] = tf32r(e0); c[j][1] = tf32r(e1);
        c[j][2] = tf32r(e2); c[j][3] = tf32r(e3);
    }
    s0 += __shfl_xor_sync(0xffffffffu, s0, 1);
    s0 += __shfl_xor_sync(0xffffffffu, s0, 2);
    s1 += __shfl_xor_sync(0xffffffffu, s1, 1);
    s1 += __shfl_xor_sync(0xffffffffu, s1, 2);
    const float inv0 = 1.0f / s0, inv1 = 1.0f / s1;

    // AV: P (c-frag -> a-frag via shfl) x V^T
    float acc[4][4];
#pragma unroll
    for (int n = 0; n < 4; n++)
#pragma unroll
        for (int q = 0; q < 4; q++) acc[n][q] = 0.f;

#pragma unroll
    for (int j = 0; j < 7; j++) {
        int src = (g << 2) + (t >> 1);
        float v0 = __shfl_sync(0xffffffffu, c[j][0], src);
        float v1 = __shfl_sync(0xffffffffu, c[j][1], src);
        float v2 = __shfl_sync(0xffffffffu, c[j][2], src);
        float v3 = __shfl_sync(0xffffffffu, c[j][3], src);
        float w0 = __shfl_sync(0xffffffffu, c[j][0], src + 2);
        float w1 = __shfl_sync(0xffffffffu, c[j][1], src + 2);
        float w2 = __shfl_sync(0xffffffffu, c[j][2], src + 2);
        float w3 = __shfl_sync(0xffffffffu, c[j][3], src + 2);
        uint32_t a[4];
        a[0] = __float_as_uint((t & 1) ? v1 : v0);
        a[1] = __float_as_uint((t & 1) ? v3 : v2);
        a[2] = __float_as_uint((t & 1) ? w1 : w0);
        a[3] = __float_as_uint((t & 1) ? w3 : w2);
#pragma unroll
        for (int n = 0; n < 4; n++) {
            int vrow = (n * 8 + g) * VSTR + j * 8 + t;
            uint32_t b0 = __float_as_uint(sm[OFF_VT + vrow]);
            uint32_t b1 = __float_as_uint(sm[OFF_VT + vrow + 4]);
            mma_tf32(acc[n], a, b0, b1);
        }
    }

    // write out (rows < 49), normalized + tf32-rounded (feeds K3's MMA)
#pragma unroll
    for (int n = 0; n < 4; n++) {
        int col = h * HD + n * 8 + 2 * t;
        if (r0 < NTOK) {
            float2 o = make_float2(tf32r(acc[n][0] * inv0),
                                   tf32r(acc[n][1] * inv0));
            *(float2*)&g_y[((size_t)b * NTOK + r0) * EMB + col] = o;
        }
        if (r0 + 8 < NTOK) {
            float2 o = make_float2(tf32r(acc[n][2] * inv1),
                                   tf32r(acc[n][3] * inv1));
            *(float2*)&g_y[((size_t)b * NTOK + r0 + 8) * EMB + col] = o;
        }
    }
}

// ---------------------------------------------------------------------------
extern "C" void kernel_launch(void* const* d_in, const int* in_sizes, int n_in,
                              void* d_out, int out_size)
{
    const float* x      = (const float*)d_in[0];
    const float* mask   = (const float*)d_in[1];
    const float* qkv_w  = (const float*)d_in[2];
    const float* qkv_b  = (const float*)d_in[3];
    const float* proj_w = (const float*)d_in[4];
    const float* proj_b = (const float*)d_in[5];
    const float* rpb    = (const float*)d_in[6];
    const int*   rel_idx= (const int*)  d_in[7];
    float* out = (float*)d_out;

    cudaFuncSetAttribute(mma_gemm<0>,
        cudaFuncAttributeMaxDynamicSharedMemorySize, SMEM_BYTES);
    cudaFuncSetAttribute(mma_gemm<1>,
        cudaFuncAttributeMaxDynamicSharedMemorySize, SMEM_BYTES);

    // K0: tf32 rounding + combined bias table
    {
        int n4 = MROWS * EMB / 4;
        cvt_tf32_kernel<0><<<(n4 + 255) / 256, 256>>>((const float4*)x, n4);
        int w4 = QKV_O * KDIM / 4;
        cvt_tf32_kernel<1><<<(w4 + 255) / 256, 256>>>((const float4*)qkv_w, w4);
        int p4 = EMB * KDIM / 4;
        cvt_tf32_kernel<2><<<(p4 + 255) / 256, 256>>>((const float4*)proj_w, p4);
        int nb = NWIN * HEADS * NTP * NSP;
        prep_bias<<<(nb + 255) / 256, 256>>>(mask, rpb, rel_idx);
    }
    // K1: qkv GEMM
    {
        dim3 grid(QKV_O / 128, MROWS / 128);
        mma_gemm<0><<<grid, 128, SMEM_BYTES>>>(qkv_b, nullptr);
    }
    // K2: attention
    {
        dim3 grid(BATCH, HEADS);
        attn_kernel<<<grid, 128>>>();
    }
    // K3: proj GEMM
    {
        dim3 grid(EMB / 128, MROWS / 128);
        mma_gemm<1><<<grid, 128, SMEM_BYTES>>>(proj_b, out);
    }
}

// round 10
// speedup vs baseline: 3.2913x; 1.0417x over previous
#include <cuda_runtime.h>
#include <cstdint>

// ---------------------------------------------------------------------------
// WindowAttention round 7:
//  K0 : round qkv_w / proj_w to tf32 (tiny); prep combined (bias+mask)*log2e
//  K1 : qkv GEMM, tf32 mma.sync; x rounded to tf32 in-fragment (no pre-pass)
//  K2 : tensor-core attention; no-max softmax via ex2, folded log2e
//  K3 : proj GEMM
// ---------------------------------------------------------------------------

#define BATCH   4096
#define NTOK    49
#define EMB     384
#define HEADS   12
#define HD      32
#define NWIN    64
#define MROWS   (BATCH * NTOK)        // 200704
#define QKV_O   (3 * EMB)             // 1152
#define KDIM    384

#define SSTR    36
#define ABUF    (128 * SSTR)
#define SMEM_BYTES (4 * ABUF * 4)     // 73728 B

// padded attention dims
#define NTP     64
#define NSP     56

__device__ float g_qkv[(size_t)3 * BATCH * HEADS * NTOK * HD];
__device__ float g_y [(size_t)MROWS * EMB];
__device__ float g_wq[QKV_O * KDIM];
__device__ float g_wp[EMB * KDIM];
__device__ float g_comb[(size_t)NWIN * HEADS * NTP * NSP];   // 11 MB

__device__ __forceinline__ float tf32r(float x) {
    uint32_t r;
    asm("cvt.rna.tf32.f32 %0, %1;" : "=r"(r) : "f"(x));
    return __uint_as_float(r);
}
__device__ __forceinline__ float ex2(float x) {
    float y;
    asm("ex2.approx.f32 %0, %1;" : "=f"(y) : "f"(x));
    return y;
}
__device__ __forceinline__ void cpa16(uint32_t dst, const float* src) {
    asm volatile("cp.async.ca.shared.global [%0], [%1], 16;"
                 :: "r"(dst), "l"(src));
}
__device__ __forceinline__ void mma_tf32(
    float c[4], const uint32_t a[4], uint32_t b0, uint32_t b1)
{
    asm volatile(
        "mma.sync.aligned.m16n8k8.row.col.f32.tf32.tf32.f32 "
        "{%0,%1,%2,%3},{%4,%5,%6,%7},{%8,%9},{%0,%1,%2,%3};"
        : "+f"(c[0]), "+f"(c[1]), "+f"(c[2]), "+f"(c[3])
        : "r"(a[0]), "r"(a[1]), "r"(a[2]), "r"(a[3]), "r"(b0), "r"(b1));
}

// ---------------------------------------------------------------------------
// K0a: weight rounding (tiny). DST: 1 = g_wq, 2 = g_wp
// ---------------------------------------------------------------------------
template <int DST>
__global__ void cvt_tf32_kernel(const float4* __restrict__ in, int n4)
{
    int i = blockIdx.x * blockDim.x + threadIdx.x;
    if (i >= n4) return;
    float4 v = in[i];
    v.x = tf32r(v.x); v.y = tf32r(v.y); v.z = tf32r(v.z); v.w = tf32r(v.w);
    float4* outp = (DST == 1) ? (float4*)g_wq : (float4*)g_wp;
    outp[i] = v;
}

// ---------------------------------------------------------------------------
// K0b: combined table, scaled by log2(e):
// g_comb[w][h][i][j] = (mask[w,i,j] + rpb[rel_idx[i,j], h]) * log2e  (i,j<49)
//                    = -1e30                                          else
// ---------------------------------------------------------------------------
__global__ void prep_bias(const float* __restrict__ mask,
                          const float* __restrict__ rpb,
                          const int* __restrict__ rel_idx)
{
    int idx = blockIdx.x * blockDim.x + threadIdx.x;
    const int total = NWIN * HEADS * NTP * NSP;
    if (idx >= total) return;
    int j = idx % NSP;
    int i = (idx / NSP) % NTP;
    int h = (idx / (NSP * NTP)) % HEADS;
    int w = idx / (NSP * NTP * HEADS);
    float v = -1e30f;
    if (i < NTOK && j < NTOK)
        v = (mask[((size_t)w * NTOK + i) * NTOK + j]
           + rpb[rel_idx[i * NTOK + j] * HEADS + h]) * 1.4426950408889634f;
    g_comb[idx] = v;
}

// ---------------------------------------------------------------------------
// K1/K3: tf32 MMA GEMM. MODE 0: A = x param (rounded in-fragment), W = g_wq,
// scatter -> g_qkv.  MODE 1: A = g_y (pre-rounded), W = g_wp, -> out.
// ---------------------------------------------------------------------------
template <int MODE>
__global__ void __launch_bounds__(128, 2) mma_gemm(
    const float* __restrict__ Aext,
    const float* __restrict__ bias, float* __restrict__ out)
{
    extern __shared__ float smem[];

    const float* A = (MODE == 0) ? Aext : g_y;
    const float* W = (MODE == 0) ? g_wq : g_wp;

    const int t     = threadIdx.x;
    const int mBase = blockIdx.y * 128;
    const int oBase = blockIdx.x * 128;
    const int warp  = t >> 5, lane = t & 31;
    const int g     = lane >> 2, tig = lane & 3;
    const int mOff  = (warp & 1) * 64;
    const int nOff  = (warp >> 1) * 64;

    const float* Ap = A + (size_t)mBase * KDIM;
    const float* Wp = W + (size_t)oBase * KDIM;

    const int lr = t >> 3;
    const int kq = (t & 7) << 2;
    const uint32_t sA = (uint32_t)__cvta_generic_to_shared(smem);

    float acc[4][8][4];
#pragma unroll
    for (int mi = 0; mi < 4; mi++)
#pragma unroll
        for (int ni = 0; ni < 8; ni++)
#pragma unroll
            for (int j = 0; j < 4; j++) acc[mi][ni][j] = 0.f;

    auto load_chunk = [&](int k0, int buf) {
        uint32_t aB = sA + (uint32_t)(buf * ABUF) * 4u;
        uint32_t bB = sA + (uint32_t)((2 + buf) * ABUF) * 4u;
#pragma unroll
        for (int i = 0; i < 8; i++) {
            int row = lr + 16 * i;
            cpa16(aB + (uint32_t)(row * SSTR + kq) * 4u,
                  Ap + (size_t)row * KDIM + k0 + kq);
            cpa16(bB + (uint32_t)(row * SSTR + kq) * 4u,
                  Wp + (size_t)row * KDIM + k0 + kq);
        }
        asm volatile("cp.async.commit_group;");
    };

    // A-fragment load: round to tf32 in-register for MODE 0 (raw x input)
    auto ldA = [&](const float* p) -> uint32_t {
        float v = *p;
        if (MODE == 0) v = tf32r(v);
        return __float_as_uint(v);
    };

    load_chunk(0, 0);

    const int NCHk = KDIM / 32;
    for (int c = 0; c < NCHk; c++) {
        if (c + 1 < NCHk) {
            load_chunk((c + 1) * 32, (c + 1) & 1);
            asm volatile("cp.async.wait_group 1;");
        } else {
            asm volatile("cp.async.wait_group 0;");
        }
        __syncthreads();

        const float* Asb = smem + (c & 1) * ABUF;
        const float* Bsb = smem + (2 + (c & 1)) * ABUF;

#pragma unroll
        for (int kk = 0; kk < 32; kk += 8) {
            uint32_t a[4][4], b[8][2];
#pragma unroll
            for (int mi = 0; mi < 4; mi++) {
                int r = mOff + mi * 16 + g;
                a[mi][0] = ldA(&Asb[r * SSTR + kk + tig]);
                a[mi][1] = ldA(&Asb[(r + 8) * SSTR + kk + tig]);
                a[mi][2] = ldA(&Asb[r * SSTR + kk + tig + 4]);
                a[mi][3] = ldA(&Asb[(r + 8) * SSTR + kk + tig + 4]);
            }
#pragma unroll
            for (int ni = 0; ni < 8; ni++) {
                int cc = nOff + ni * 8 + g;
                b[ni][0] = __float_as_uint(Bsb[cc * SSTR + kk + tig]);
                b[ni][1] = __float_as_uint(Bsb[cc * SSTR + kk + tig + 4]);
            }
#pragma unroll
            for (int mi = 0; mi < 4; mi++)
#pragma unroll
                for (int ni = 0; ni < 8; ni++)
                    mma_tf32(acc[mi][ni], a[mi], b[ni][0], b[ni][1]);
        }
        __syncthreads();
    }

#pragma unroll
    for (int mi = 0; mi < 4; mi++) {
#pragma unroll
        for (int ni = 0; ni < 8; ni++) {
            int col = oBase + nOff + ni * 8 + 2 * tig;
            float b0 = __ldg(bias + col);
            float b1 = __ldg(bias + col + 1);
#pragma unroll
            for (int half = 0; half < 2; half++) {
                int m = mBase + mOff + mi * 16 + g + half * 8;
                float v0 = acc[mi][ni][2 * half + 0] + b0;
                float v1 = acc[mi][ni][2 * half + 1] + b1;
                if (MODE == 0) {
                    int s = col / EMB;
                    int r = col - s * EMB;
                    int h = r >> 5;
                    int bb = m / NTOK;
                    int nn = m - bb * NTOK;
                    size_t idx = ((((size_t)s * BATCH + bb) * HEADS + h) * NTOK
                                  + nn) * HD + (r & 31);
                    *(float2*)&g_qkv[idx] = make_float2(v0, v1);
                } else {
                    *(float2*)&out[(size_t)m * EMB + col] = make_float2(v0, v1);
                }
            }
        }
    }
}

// ---------------------------------------------------------------------------
// K2: tensor-core attention. One CTA (128 thr) per (b,h).
// QK = tf32 3x split; softmax = ex2 (no max subtraction); AV = tf32.
// ---------------------------------------------------------------------------
#define QSTR 33
#define VSTR 57
#define OFF_QH 0
#define OFF_QL (OFF_QH + NTP * QSTR)          // 2112
#define OFF_KH (OFF_QL + NTP * QSTR)          // 4224
#define OFF_KL (OFF_KH + NSP * QSTR)          // 6072
#define OFF_VT (OFF_KL + NSP * QSTR)          // 7920
#define SM_TOT (OFF_VT + HD * VSTR)           // 9744 floats

__global__ void __launch_bounds__(128) attn_kernel()
{
    const int b = blockIdx.x;
    const int h = blockIdx.y;
    const int tid = threadIdx.x;

    __shared__ __align__(16) float sm[SM_TOT];

    // zero only K/V regions (padding there must be 0; Q garbage is confined
    // to unwritten output rows)
    for (int i = OFF_KH + tid; i < SM_TOT; i += 128) sm[i] = 0.f;
    __syncthreads();

    const size_t stride = (size_t)NTOK * HD;
    const size_t qoff = (((size_t)0 * BATCH + b) * HEADS + h) * stride;
    const size_t koff = (((size_t)1 * BATCH + b) * HEADS + h) * stride;
    const size_t voff = (((size_t)2 * BATCH + b) * HEADS + h) * stride;

    // stage Q (hi/lo), K (hi/lo), V^T
    for (int i = tid; i < (NTOK * HD) / 4; i += 128) {
        int row = i >> 3, col = (i & 7) * 4;
        float4 q = ((const float4*)(g_qkv + qoff))[i];
        float4 k = ((const float4*)(g_qkv + koff))[i];
        float4 v = ((const float4*)(g_qkv + voff))[i];
        float qa[4] = {q.x, q.y, q.z, q.w};
        float ka[4] = {k.x, k.y, k.z, k.w};
        float va[4] = {v.x, v.y, v.z, v.w};
#pragma unroll
        for (int c = 0; c < 4; c++) {
            float qh = tf32r(qa[c]);
            float kh = tf32r(ka[c]);
            sm[OFF_QH + row * QSTR + col + c] = qh;
            sm[OFF_QL + row * QSTR + col + c] = tf32r(qa[c] - qh);
            sm[OFF_KH + row * QSTR + col + c] = kh;
            sm[OFF_KL + row * QSTR + col + c] = tf32r(ka[c] - kh);
            sm[OFF_VT + (col + c) * VSTR + row] = tf32r(va[c]);
        }
    }
    __syncthreads();

    const int wid  = tid >> 5, lane = tid & 31;
    const int g    = lane >> 2, t = lane & 3;
    const int r0   = wid * 16 + g;

    uint32_t ah[4][4], al[4][4];
#pragma unroll
    for (int kc = 0; kc < 4; kc++) {
        int base = kc * 8 + t;
        ah[kc][0] = __float_as_uint(sm[OFF_QH + r0 * QSTR + base]);
        ah[kc][1] = __float_as_uint(sm[OFF_QH + (r0 + 8) * QSTR + base]);
        ah[kc][2] = __float_as_uint(sm[OFF_QH + r0 * QSTR + base + 4]);
        ah[kc][3] = __float_as_uint(sm[OFF_QH + (r0 + 8) * QSTR + base + 4]);
        al[kc][0] = __float_as_uint(sm[OFF_QL + r0 * QSTR + base]);
        al[kc][1] = __float_as_uint(sm[OFF_QL + (r0 + 8) * QSTR + base]);
        al[kc][2] = __float_as_uint(sm[OFF_QL + r0 * QSTR + base + 4]);
        al[kc][3] = __float_as_uint(sm[OFF_QL + (r0 + 8) * QSTR + base + 4]);
    }

    float c[7][4];
#pragma unroll
    for (int j = 0; j < 7; j++)
#pragma unroll
        for (int q = 0; q < 4; q++) c[j][q] = 0.f;

#pragma unroll
    for (int j = 0; j < 7; j++) {
#pragma unroll
        for (int kc = 0; kc < 4; kc++) {
            int krow = (j * 8 + g) * QSTR + kc * 8 + t;
            uint32_t bh0 = __float_as_uint(sm[OFF_KH + krow]);
            uint32_t bh1 = __float_as_uint(sm[OFF_KH + krow + 4]);
            uint32_t bl0 = __float_as_uint(sm[OFF_KL + krow]);
            uint32_t bl1 = __float_as_uint(sm[OFF_KL + krow + 4]);
            mma_tf32(c[j], ah[kc], bh0, bh1);
            mma_tf32(c[j], ah[kc], bl0, bl1);
            mma_tf32(c[j], al[kc], bh0, bh1);
        }
    }

    // P = exp2(c*scale*log2e + comb2), no max subtraction
    const float scale2 = 0.17677669529663687f * 1.4426950408889634f;
    const float* comb = g_comb
        + (((size_t)(b & (NWIN - 1)) * HEADS + h) * NTP) * NSP;

    float s0 = 0.f, s1 = 0.f;
#pragma unroll
    for (int j = 0; j < 7; j++) {
        float2 m0 = *(const float2*)(comb + r0 * NSP + j * 8 + 2 * t);
        float2 m1 = *(const float2*)(comb + (r0 + 8) * NSP + j * 8 + 2 * t);
        float e0 = ex2(fmaf(c[j][0], scale2, m0.x));
        float e1 = ex2(fmaf(c[j][1], scale2, m0.y));
        float e2 = ex2(fmaf(c[j][2], scale2, m1.x));
        float e3 = ex2(fmaf(c[j][3], scale2, m1.y));
        s0 += e0 + e1; s1 += e2 + e3;
        c[j][0] = tf32r(e0); c[j][1] = tf32r(e1);
        c[j][2] = tf32r(e2); c[j][3] = tf32r(e3);
    }
    s0 += __shfl_xor_sync(0xffffffffu, s0, 1);
    s0 += __shfl_xor_sync(0xffffffffu, s0, 2);
    s1 += __shfl_xor_sync(0xffffffffu, s1, 1);
    s1 += __shfl_xor_sync(0xffffffffu, s1, 2);
    const float inv0 = 1.0f / s0, inv1 = 1.0f / s1;

    // AV: P (c-frag -> a-frag via shfl) x V^T
    float acc[4][4];
#pragma unroll
    for (int n = 0; n < 4; n++)
#pragma unroll
        for (int q = 0; q < 4; q++) acc[n][q] = 0.f;

#pragma unroll
    for (int j = 0; j < 7; j++) {
        int src = (g << 2) + (t >> 1);
        float v0 = __shfl_sync(0xffffffffu, c[j][0], src);
        float v1 = __shfl_sync(0xffffffffu, c[j][1], src);
        float v2 = __shfl_sync(0xffffffffu, c[j][2], src);
        float v3 = __shfl_sync(0xffffffffu, c[j][3], src);
        float w0 = __shfl_sync(0xffffffffu, c[j][0], src + 2);
        float w1 = __shfl_sync(0xffffffffu, c[j][1], src + 2);
        float w2 = __shfl_sync(0xffffffffu, c[j][2], src + 2);
        float w3 = __shfl_sync(0xffffffffu, c[j][3], src + 2);
        uint32_t a[4];
        a[0] = __float_as_uint((t & 1) ? v1 : v0);
        a[1] = __float_as_uint((t & 1) ? v3 : v2);
        a[2] = __float_as_uint((t & 1) ? w1 : w0);
        a[3] = __float_as_uint((t & 1) ? w3 : w2);
#pragma unroll
        for (int n = 0; n < 4; n++) {
            int vrow = (n * 8 + g) * VSTR + j * 8 + t;
            uint32_t b0 = __float_as_uint(sm[OFF_VT + vrow]);
            uint32_t b1 = __float_as_uint(sm[OFF_VT + vrow + 4]);
            mma_tf32(acc[n], a, b0, b1);
        }
    }

#pragma unroll
    for (int n = 0; n < 4; n++) {
        int col = h * HD + n * 8 + 2 * t;
        if (r0 < NTOK) {
            float2 o = make_float2(tf32r(acc[n][0] * inv0),
                                   tf32r(acc[n][1] * inv0));
            *(float2*)&g_y[((size_t)b * NTOK + r0) * EMB + col] = o;
        }
        if (r0 + 8 < NTOK) {
            float2 o = make_float2(tf32r(acc[n][2] * inv1),
                                   tf32r(acc[n][3] * inv1));
            *(float2*)&g_y[((size_t)b * NTOK + r0 + 8) * EMB + col] = o;
        }
    }
}

// ---------------------------------------------------------------------------
extern "C" void kernel_launch(void* const* d_in, const int* in_sizes, int n_in,
                              void* d_out, int out_size)
{
    const float* x      = (const float*)d_in[0];
    const float* mask   = (const float*)d_in[1];
    const float* qkv_w  = (const float*)d_in[2];
    const float* qkv_b  = (const float*)d_in[3];
    const float* proj_w = (const float*)d_in[4];
    const float* proj_b = (const float*)d_in[5];
    const float* rpb    = (const float*)d_in[6];
    const int*   rel_idx= (const int*)  d_in[7];
    float* out = (float*)d_out;

    cudaFuncSetAttribute(mma_gemm<0>,
        cudaFuncAttributeMaxDynamicSharedMemorySize, SMEM_BYTES);
    cudaFuncSetAttribute(mma_gemm<1>,
        cudaFuncAttributeMaxDynamicSharedMemorySize, SMEM_BYTES);

    // K0: weight rounding (tiny) + combined bias table
    {
        int w4 = QKV_O * KDIM / 4;
        cvt_tf32_kernel<1><<<(w4 + 255) / 256, 256>>>((const float4*)qkv_w, w4);
        int p4 = EMB * KDIM / 4;
        cvt_tf32_kernel<2><<<(p4 + 255) / 256, 256>>>((const float4*)proj_w, p4);
        int nb = NWIN * HEADS * NTP * NSP;
        prep_bias<<<(nb + 255) / 256, 256>>>(mask, rpb, rel_idx);
    }
    // K1: qkv GEMM (x rounded in-fragment)
    {
        dim3 grid(QKV_O / 128, MROWS / 128);
        mma_gemm<0><<<grid, 128, SMEM_BYTES>>>(x, qkv_b, nullptr);
    }
    // K2: attention
    {
        dim3 grid(BATCH, HEADS);
        attn_kernel<<<grid, 128>>>();
    }
    // K3: proj GEMM
    {
        dim3 grid(EMB / 128, MROWS / 128);
        mma_gemm<1><<<grid, 128, SMEM_BYTES>>>(g_y /*unused*/, proj_b, out);
    }
}

// round 13
// speedup vs baseline: 3.4306x; 1.0423x over previous
#include <cuda_runtime.h>
#include <cstdint>

// ---------------------------------------------------------------------------
// WindowAttention round 11:
//  K0 : round qkv_w / proj_w to tf32 (tiny); prep combined (bias+mask)*log2e
//  K1 : qkv GEMM, tf32 mma.sync; x rounded to tf32 in-fragment
//  K2 : tensor-core attention, restructured: Q fragments direct from gmem
//       (register hi/lo split), smem only K(hi/lo)+V^T, kc-outer QK loop,
//       6 CTAs/SM target
//  K3 : proj GEMM
// ---------------------------------------------------------------------------

#define BATCH   4096
#define NTOK    49
#define EMB     384
#define HEADS   12
#define HD      32
#define NWIN    64
#define MROWS   (BATCH * NTOK)        // 200704
#define QKV_O   (3 * EMB)             // 1152
#define KDIM    384

#define SSTR    36
#define ABUF    (128 * SSTR)
#define SMEM_BYTES (4 * ABUF * 4)     // 73728 B

// padded attention dims
#define NTP     64
#define NSP     56

__device__ float g_qkv[(size_t)3 * BATCH * HEADS * NTOK * HD];
__device__ float g_y [(size_t)MROWS * EMB];
__device__ float g_wq[QKV_O * KDIM];
__device__ float g_wp[EMB * KDIM];
__device__ float g_comb[(size_t)NWIN * HEADS * NTP * NSP];   // 11 MB

__device__ __forceinline__ float tf32r(float x) {
    uint32_t r;
    asm("cvt.rna.tf32.f32 %0, %1;" : "=r"(r) : "f"(x));
    return __uint_as_float(r);
}
__device__ __forceinline__ float ex2(float x) {
    float y;
    asm("ex2.approx.f32 %0, %1;" : "=f"(y) : "f"(x));
    return y;
}
__device__ __forceinline__ void cpa16(uint32_t dst, const float* src) {
    asm volatile("cp.async.ca.shared.global [%0], [%1], 16;"
                 :: "r"(dst), "l"(src));
}
__device__ __forceinline__ void mma_tf32(
    float c[4], const uint32_t a[4], uint32_t b0, uint32_t b1)
{
    asm volatile(
        "mma.sync.aligned.m16n8k8.row.col.f32.tf32.tf32.f32 "
        "{%0,%1,%2,%3},{%4,%5,%6,%7},{%8,%9},{%0,%1,%2,%3};"
        : "+f"(c[0]), "+f"(c[1]), "+f"(c[2]), "+f"(c[3])
        : "r"(a[0]), "r"(a[1]), "r"(a[2]), "r"(a[3]), "r"(b0), "r"(b1));
}

// ---------------------------------------------------------------------------
// K0a: weight rounding (tiny). DST: 1 = g_wq, 2 = g_wp
// ---------------------------------------------------------------------------
template <int DST>
__global__ void cvt_tf32_kernel(const float4* __restrict__ in, int n4)
{
    int i = blockIdx.x * blockDim.x + threadIdx.x;
    if (i >= n4) return;
    float4 v = in[i];
    v.x = tf32r(v.x); v.y = tf32r(v.y); v.z = tf32r(v.z); v.w = tf32r(v.w);
    float4* outp = (DST == 1) ? (float4*)g_wq : (float4*)g_wp;
    outp[i] = v;
}

// ---------------------------------------------------------------------------
// K0b: combined table, scaled by log2(e)
// ---------------------------------------------------------------------------
__global__ void prep_bias(const float* __restrict__ mask,
                          const float* __restrict__ rpb,
                          const int* __restrict__ rel_idx)
{
    int idx = blockIdx.x * blockDim.x + threadIdx.x;
    const int total = NWIN * HEADS * NTP * NSP;
    if (idx >= total) return;
    int j = idx % NSP;
    int i = (idx / NSP) % NTP;
    int h = (idx / (NSP * NTP)) % HEADS;
    int w = idx / (NSP * NTP * HEADS);
    float v = -1e30f;
    if (i < NTOK && j < NTOK)
        v = (mask[((size_t)w * NTOK + i) * NTOK + j]
           + rpb[rel_idx[i * NTOK + j] * HEADS + h]) * 1.4426950408889634f;
    g_comb[idx] = v;
}

// ---------------------------------------------------------------------------
// K1/K3: tf32 MMA GEMM (round-7 engine, verified; unchanged)
// ---------------------------------------------------------------------------
template <int MODE>
__global__ void __launch_bounds__(128, 2) mma_gemm(
    const float* __restrict__ Aext,
    const float* __restrict__ bias, float* __restrict__ out)
{
    extern __shared__ float smem[];

    const float* A = (MODE == 0) ? Aext : g_y;
    const float* W = (MODE == 0) ? g_wq : g_wp;

    const int t     = threadIdx.x;
    const int mBase = blockIdx.y * 128;
    const int oBase = blockIdx.x * 128;
    const int warp  = t >> 5, lane = t & 31;
    const int g     = lane >> 2, tig = lane & 3;
    const int mOff  = (warp & 1) * 64;
    const int nOff  = (warp >> 1) * 64;

    const float* Ap = A + (size_t)mBase * KDIM;
    const float* Wp = W + (size_t)oBase * KDIM;

    const int lr = t >> 3;
    const int kq = (t & 7) << 2;
    const uint32_t sA = (uint32_t)__cvta_generic_to_shared(smem);

    float acc[4][8][4];
#pragma unroll
    for (int mi = 0; mi < 4; mi++)
#pragma unroll
        for (int ni = 0; ni < 8; ni++)
#pragma unroll
            for (int j = 0; j < 4; j++) acc[mi][ni][j] = 0.f;

    auto load_chunk = [&](int k0, int buf) {
        uint32_t aB = sA + (uint32_t)(buf * ABUF) * 4u;
        uint32_t bB = sA + (uint32_t)((2 + buf) * ABUF) * 4u;
#pragma unroll
        for (int i = 0; i < 8; i++) {
            int row = lr + 16 * i;
            cpa16(aB + (uint32_t)(row * SSTR + kq) * 4u,
                  Ap + (size_t)row * KDIM + k0 + kq);
            cpa16(bB + (uint32_t)(row * SSTR + kq) * 4u,
                  Wp + (size_t)row * KDIM + k0 + kq);
        }
        asm volatile("cp.async.commit_group;");
    };

    auto ldA = [&](const float* p) -> uint32_t {
        float v = *p;
        if (MODE == 0) v = tf32r(v);
        return __float_as_uint(v);
    };

    load_chunk(0, 0);

    const int NCHk = KDIM / 32;
    for (int c = 0; c < NCHk; c++) {
        if (c + 1 < NCHk) {
            load_chunk((c + 1) * 32, (c + 1) & 1);
            asm volatile("cp.async.wait_group 1;");
        } else {
            asm volatile("cp.async.wait_group 0;");
        }
        __syncthreads();

        const float* Asb = smem + (c & 1) * ABUF;
        const float* Bsb = smem + (2 + (c & 1)) * ABUF;

#pragma unroll
        for (int kk = 0; kk < 32; kk += 8) {
            uint32_t a[4][4], b[8][2];
#pragma unroll
            for (int mi = 0; mi < 4; mi++) {
                int r = mOff + mi * 16 + g;
                a[mi][0] = ldA(&Asb[r * SSTR + kk + tig]);
                a[mi][1] = ldA(&Asb[(r + 8) * SSTR + kk + tig]);
                a[mi][2] = ldA(&Asb[r * SSTR + kk + tig + 4]);
                a[mi][3] = ldA(&Asb[(r + 8) * SSTR + kk + tig + 4]);
            }
#pragma unroll
            for (int ni = 0; ni < 8; ni++) {
                int cc = nOff + ni * 8 + g;
                b[ni][0] = __float_as_uint(Bsb[cc * SSTR + kk + tig]);
                b[ni][1] = __float_as_uint(Bsb[cc * SSTR + kk + tig + 4]);
            }
#pragma unroll
            for (int mi = 0; mi < 4; mi++)
#pragma unroll
                for (int ni = 0; ni < 8; ni++)
                    mma_tf32(acc[mi][ni], a[mi], b[ni][0], b[ni][1]);
        }
        __syncthreads();
    }

#pragma unroll
    for (int mi = 0; mi < 4; mi++) {
#pragma unroll
        for (int ni = 0; ni < 8; ni++) {
            int col = oBase + nOff + ni * 8 + 2 * tig;
            float b0 = __ldg(bias + col);
            float b1 = __ldg(bias + col + 1);
#pragma unroll
            for (int half = 0; half < 2; half++) {
                int m = mBase + mOff + mi * 16 + g + half * 8;
                float v0 = acc[mi][ni][2 * half + 0] + b0;
                float v1 = acc[mi][ni][2 * half + 1] + b1;
                if (MODE == 0) {
                    int s = col / EMB;
                    int r = col - s * EMB;
                    int h = r >> 5;
                    int bb = m / NTOK;
                    int nn = m - bb * NTOK;
                    size_t idx = ((((size_t)s * BATCH + bb) * HEADS + h) * NTOK
                                  + nn) * HD + (r & 31);
                    *(float2*)&g_qkv[idx] = make_float2(v0, v1);
                } else {
                    *(float2*)&out[(size_t)m * EMB + col] = make_float2(v0, v1);
                }
            }
        }
    }
}

// ---------------------------------------------------------------------------
// K2: tensor-core attention, lean. One CTA (128 thr) per (b,h).
// smem: K hi/lo + V^T only (21.6 KB). Q fragments straight from gmem with
// register hi/lo split. kc-outer QK loop. No-max ex2 softmax.
// ---------------------------------------------------------------------------
#define KSTR 33
#define VSTR 57
#define OFF_KH 0
#define OFF_KL (NSP * KSTR)                   // 1848
#define OFF_VT (2 * NSP * KSTR)               // 3696
#define SM_TOT (OFF_VT + HD * VSTR)           // 5520 floats = 22080 B

__global__ void __launch_bounds__(128, 6) attn_kernel()
{
    const int b = blockIdx.x;
    const int h = blockIdx.y;
    const int tid = threadIdx.x;

    __shared__ __align__(16) float sm[SM_TOT];

    // zero only padding: K rows 49..55 (hi+lo), V^T cols 49..55
    for (int i = tid; i < 7 * KSTR; i += 128) {
        sm[OFF_KH + 49 * KSTR + i] = 0.f;
        sm[OFF_KL + 49 * KSTR + i] = 0.f;
    }
    for (int i = tid; i < HD * 8; i += 128)
        sm[OFF_VT + (i >> 3) * VSTR + 49 + (i & 7)] = 0.f;

    const size_t stride = (size_t)NTOK * HD;
    const size_t qoff = (((size_t)0 * BATCH + b) * HEADS + h) * stride;
    const size_t koff = (((size_t)1 * BATCH + b) * HEADS + h) * stride;
    const size_t voff = (((size_t)2 * BATCH + b) * HEADS + h) * stride;

    // stage K (hi/lo) and V^T
    for (int i = tid; i < (NTOK * HD) / 4; i += 128) {
        int row = i >> 3, col = (i & 7) * 4;
        float4 k = ((const float4*)(g_qkv + koff))[i];
        float4 v = ((const float4*)(g_qkv + voff))[i];
        float ka[4] = {k.x, k.y, k.z, k.w};
        float va[4] = {v.x, v.y, v.z, v.w};
#pragma unroll
        for (int c = 0; c < 4; c++) {
            float kh = tf32r(ka[c]);
            sm[OFF_KH + row * KSTR + col + c] = kh;
            sm[OFF_KL + row * KSTR + col + c] = tf32r(ka[c] - kh);
            sm[OFF_VT + (col + c) * VSTR + row] = tf32r(va[c]);
        }
    }
    __syncthreads();

    const int wid  = tid >> 5, lane = tid & 31;
    const int g    = lane >> 2, t = lane & 3;
    const int r0   = wid * 16 + g;          // rows r0, r0+8 (garbage if >=49)

    const float* gq = g_qkv + qoff;

    float c[7][4];
#pragma unroll
    for (int j = 0; j < 7; j++)
#pragma unroll
        for (int q = 0; q < 4; q++) c[j][q] = 0.f;

    // QK^T: kc outer; Q fragments from gmem (L1 lines, 1 row = 1 line)
#pragma unroll
    for (int kc = 0; kc < 4; kc++) {
        const int cb = kc * 8 + t;
        float q0 = __ldg(gq + (size_t)r0 * HD + cb);
        float q1 = __ldg(gq + (size_t)(r0 + 8) * HD + cb);
        float q2 = __ldg(gq + (size_t)r0 * HD + cb + 4);
        float q3 = __ldg(gq + (size_t)(r0 + 8) * HD + cb + 4);
        float h0 = tf32r(q0), h1 = tf32r(q1), h2 = tf32r(q2), h3 = tf32r(q3);
        uint32_t ah[4] = {__float_as_uint(h0), __float_as_uint(h1),
                          __float_as_uint(h2), __float_as_uint(h3)};
        uint32_t al[4] = {__float_as_uint(tf32r(q0 - h0)),
                          __float_as_uint(tf32r(q1 - h1)),
                          __float_as_uint(tf32r(q2 - h2)),
                          __float_as_uint(tf32r(q3 - h3))};
#pragma unroll
        for (int j = 0; j < 7; j++) {
            int krow = (j * 8 + g) * KSTR + kc * 8 + t;
            uint32_t bh0 = __float_as_uint(sm[OFF_KH + krow]);
            uint32_t bh1 = __float_as_uint(sm[OFF_KH + krow + 4]);
            uint32_t bl0 = __float_as_uint(sm[OFF_KL + krow]);
            uint32_t bl1 = __float_as_uint(sm[OFF_KL + krow + 4]);
            mma_tf32(c[j], ah, bh0, bh1);
            mma_tf32(c[j], ah, bl0, bl1);
            mma_tf32(c[j], al, bh0, bh1);
        }
    }

    // P = exp2(c*scale*log2e + comb), no max subtraction
    const float scale2 = 0.17677669529663687f * 1.4426950408889634f;
    const float* comb = g_comb
        + (((size_t)(b & (NWIN - 1)) * HEADS + h) * NTP) * NSP;

    float s0 = 0.f, s1 = 0.f;
#pragma unroll
    for (int j = 0; j < 7; j++) {
        float2 m0 = *(const float2*)(comb + r0 * NSP + j * 8 + 2 * t);
        float2 m1 = *(const float2*)(comb + (r0 + 8) * NSP + j * 8 + 2 * t);
        float e0 = ex2(fmaf(c[j][0], scale2, m0.x));
        float e1 = ex2(fmaf(c[j][1], scale2, m0.y));
        float e2 = ex2(fmaf(c[j][2], scale2, m1.x));
        float e3 = ex2(fmaf(c[j][3], scale2, m1.y));
        s0 += e0 + e1; s1 += e2 + e3;
        c[j][0] = tf32r(e0); c[j][1] = tf32r(e1);
        c[j][2] = tf32r(e2); c[j][3] = tf32r(e3);
    }
    s0 += __shfl_xor_sync(0xffffffffu, s0, 1);
    s0 += __shfl_xor_sync(0xffffffffu, s0, 2);
    s1 += __shfl_xor_sync(0xffffffffu, s1, 1);
    s1 += __shfl_xor_sync(0xffffffffu, s1, 2);
    const float inv0 = 1.0f / s0, inv1 = 1.0f / s1;

    // AV: P (c-frag -> a-frag via shfl) x V^T
    float acc[4][4];
#pragma unroll
    for (int n = 0; n < 4; n++)
#pragma unroll
        for (int q = 0; q < 4; q++) acc[n][q] = 0.f;

#pragma unroll
    for (int j = 0; j < 7; j++) {
        int src = (g << 2) + (t >> 1);
        float v0 = __shfl_sync(0xffffffffu, c[j][0], src);
        float v1 = __shfl_sync(0xffffffffu, c[j][1], src);
        float v2 = __shfl_sync(0xffffffffu, c[j][2], src);
        float v3 = __shfl_sync(0xffffffffu, c[j][3], src);
        float w0 = __shfl_sync(0xffffffffu, c[j][0], src + 2);
        float w1 = __shfl_sync(0xffffffffu, c[j][1], src + 2);
        float w2 = __shfl_sync(0xffffffffu, c[j][2], src + 2);
        float w3 = __shfl_sync(0xffffffffu, c[j][3], src + 2);
        uint32_t a[4];
        a[0] = __float_as_uint((t & 1) ? v1 : v0);
        a[1] = __float_as_uint((t & 1) ? v3 : v2);
        a[2] = __float_as_uint((t & 1) ? w1 : w0);
        a[3] = __float_as_uint((t & 1) ? w3 : w2);
#pragma unroll
        for (int n = 0; n < 4; n++) {
            int vrow = (n * 8 + g) * VSTR + j * 8 + t;
            uint32_t b0 = __float_as_uint(sm[OFF_VT + vrow]);
            uint32_t b1 = __float_as_uint(sm[OFF_VT + vrow + 4]);
            mma_tf32(acc[n], a, b0, b1);
        }
    }

#pragma unroll
    for (int n = 0; n < 4; n++) {
        int col = h * HD + n * 8 + 2 * t;
        if (r0 < NTOK) {
            float2 o = make_float2(tf32r(acc[n][0] * inv0),
                                   tf32r(acc[n][1] * inv0));
            *(float2*)&g_y[((size_t)b * NTOK + r0) * EMB + col] = o;
        }
        if (r0 + 8 < NTOK) {
            float2 o = make_float2(tf32r(acc[n][2] * inv1),
                                   tf32r(acc[n][3] * inv1));
            *(float2*)&g_y[((size_t)b * NTOK + r0 + 8) * EMB + col] = o;
        }
    }
}

// ---------------------------------------------------------------------------
extern "C" void kernel_launch(void* const* d_in, const int* in_sizes, int n_in,
                              void* d_out, int out_size)
{
    const float* x      = (const float*)d_in[0];
    const float* mask   = (const float*)d_in[1];
    const float* qkv_w  = (const float*)d_in[2];
    const float* qkv_b  = (const float*)d_in[3];
    const float* proj_w = (const float*)d_in[4];
    const float* proj_b = (const float*)d_in[5];
    const float* rpb    = (const float*)d_in[6];
    const int*   rel_idx= (const int*)  d_in[7];
    float* out = (float*)d_out;

    cudaFuncSetAttribute(mma_gemm<0>,
        cudaFuncAttributeMaxDynamicSharedMemorySize, SMEM_BYTES);
    cudaFuncSetAttribute(mma_gemm<1>,
        cudaFuncAttributeMaxDynamicSharedMemorySize, SMEM_BYTES);

    // K0: weight rounding (tiny) + combined bias table
    {
        int w4 = QKV_O * KDIM / 4;
        cvt_tf32_kernel<1><<<(w4 + 255) / 256, 256>>>((const float4*)qkv_w, w4);
        int p4 = EMB * KDIM / 4;
        cvt_tf32_kernel<2><<<(p4 + 255) / 256, 256>>>((const float4*)proj_w, p4);
        int nb = NWIN * HEADS * NTP * NSP;
        prep_bias<<<(nb + 255) / 256, 256>>>(mask, rpb, rel_idx);
    }
    // K1: qkv GEMM (x rounded in-fragment)
    {
        dim3 grid(QKV_O / 128, MROWS / 128);
        mma_gemm<0><<<grid, 128, SMEM_BYTES>>>(x, qkv_b, nullptr);
    }
    // K2: attention
    {
        dim3 grid(BATCH, HEADS);
        attn_kernel<<<grid, 128>>>();
    }
    // K3: proj GEMM
    {
        dim3 grid(EMB / 128, MROWS / 128);
        mma_gemm<1><<<grid, 128, SMEM_BYTES>>>(g_y /*unused*/, proj_b, out);
    }
}